// round 12
// baseline (speedup 1.0000x reference)
#include <cuda_runtime.h>
#include <cuda_bf16.h>
#include <math.h>
#include <stdint.h>

// Problem constants
#define BB 4
#define NN 4096
#define CC 256
#define HH 8
#define GG 4
#define DD 32
#define NG 1024
#define QSCL (0.17677669529663687f * 1.4426950408889634f)  // 1/sqrt(32)*log2(e)

#define XTOT  (BB * NN * CC)
#define WQTOT (3 * CC * CC)
#define WPTOT (CC * CC)

// Scratch (device globals; allocation-free)
__device__ float g_X[XTOT];
__device__ float g_Wq[WQTOT];
__device__ float g_Wp[WPTOT];
__device__ float g_Q[BB * GG * HH * NG * DD];
__device__ __nv_bfloat16 g_Khi[BB * GG * HH * NG * DD];   // [bgh][i][d]
__device__ __nv_bfloat16 g_Klo[BB * GG * HH * NG * DD];
__device__ __nv_bfloat16 g_Vhi[BB * GG * HH * NG * DD];   // [bgh][i][d]
__device__ __nv_bfloat16 g_Vlo[BB * GG * HH * NG * DD];
__device__ float g_O[BB * NN * CC];                        // tf32 bits

// ---------------------------------------------------------------------------
// PTX helpers
// ---------------------------------------------------------------------------
__device__ __forceinline__ void mma8(float c[4], const uint32_t a[4],
                                     uint32_t b0, uint32_t b1) {
    asm volatile(
        "mma.sync.aligned.m16n8k8.row.col.f32.tf32.tf32.f32 "
        "{%0,%1,%2,%3}, {%4,%5,%6,%7}, {%8,%9}, {%0,%1,%2,%3};"
        : "+f"(c[0]), "+f"(c[1]), "+f"(c[2]), "+f"(c[3])
        : "r"(a[0]), "r"(a[1]), "r"(a[2]), "r"(a[3]), "r"(b0), "r"(b1));
}
__device__ __forceinline__ void mma16(float c[4], const uint32_t a[4],
                                      uint32_t b0, uint32_t b1) {
    asm volatile(
        "mma.sync.aligned.m16n8k16.row.col.f32.bf16.bf16.f32 "
        "{%0,%1,%2,%3}, {%4,%5,%6,%7}, {%8,%9}, {%0,%1,%2,%3};"
        : "+f"(c[0]), "+f"(c[1]), "+f"(c[2]), "+f"(c[3])
        : "r"(a[0]), "r"(a[1]), "r"(a[2]), "r"(a[3]), "r"(b0), "r"(b1));
}
__device__ __forceinline__ uint32_t to_tf32(float x) {
    uint32_t h; asm("cvt.rna.tf32.f32 %0, %1;" : "=r"(h) : "f"(x)); return h;
}
__device__ __forceinline__ float ex2(float x) {
    float r; asm("ex2.approx.ftz.f32 %0, %1;" : "=f"(r) : "f"(x)); return r;
}
__device__ __forceinline__ uint32_t packbf(float x, float y) {
    uint32_t r; asm("cvt.rn.bf16x2.f32 %0, %1, %2;" : "=r"(r) : "f"(y), "f"(x));
    return r;
}
__device__ __forceinline__ void splitbf(float x, float y, uint32_t& h, uint32_t& l) {
    h = packbf(x, y);
    __nv_bfloat162 hb = *reinterpret_cast<__nv_bfloat162*>(&h);
    l = packbf(x - __bfloat162float(hb.x), y - __bfloat162float(hb.y));
}
__device__ __forceinline__ uint32_t sptr(const void* p) {
    return (uint32_t)__cvta_generic_to_shared(p);
}
__device__ __forceinline__ void ldsm4(uint32_t addr, uint32_t& r0, uint32_t& r1,
                                      uint32_t& r2, uint32_t& r3) {
    asm volatile("ldmatrix.sync.aligned.m8n8.x4.shared.b16 {%0,%1,%2,%3}, [%4];"
                 : "=r"(r0), "=r"(r1), "=r"(r2), "=r"(r3) : "r"(addr));
}
__device__ __forceinline__ void ldsm4t(uint32_t addr, uint32_t& r0, uint32_t& r1,
                                       uint32_t& r2, uint32_t& r3) {
    asm volatile("ldmatrix.sync.aligned.m8n8.x4.trans.shared.b16 {%0,%1,%2,%3}, [%4];"
                 : "=r"(r0), "=r"(r1), "=r"(r2), "=r"(r3) : "r"(addr));
}
__device__ __forceinline__ void cpa16(uint32_t dst, const void* src) {
    asm volatile("cp.async.cg.shared.global [%0], [%1], 16;" :: "r"(dst), "l"(src));
}
#define CP_COMMIT() asm volatile("cp.async.commit_group;")
#define CP_WAIT0()  asm volatile("cp.async.wait_group 0;")

// ---------------------------------------------------------------------------
// Kernel 0: pre-convert x, w_qkv, w_proj to tf32 bit patterns
// ---------------------------------------------------------------------------
__global__ __launch_bounds__(256) void prep_kernel(
    const float* __restrict__ x, const float* __restrict__ wq,
    const float* __restrict__ wp)
{
    int i = blockIdx.x * 256 + threadIdx.x;
    const float4* src; float4* dst; int off;
    if (i < XTOT / 4)                { src = (const float4*)x;  dst = (float4*)g_X;  off = i; }
    else if (i < (XTOT + WQTOT) / 4) { src = (const float4*)wq; dst = (float4*)g_Wq; off = i - XTOT / 4; }
    else                             { src = (const float4*)wp; dst = (float4*)g_Wp; off = i - (XTOT + WQTOT) / 4; }
    float4 v = src[off];
    v.x = __uint_as_float(to_tf32(v.x));
    v.y = __uint_as_float(to_tf32(v.y));
    v.z = __uint_as_float(to_tf32(v.z));
    v.w = __uint_as_float(to_tf32(v.w));
    dst[off] = v;
}

// ---------------------------------------------------------------------------
// Kernel 1: QKV = gather(g_X, idx) @ g_Wq^T  (tf32 mma, 128x128 tile)
// 8 warps (4m x 2n), warp tile 32x64, k-slab 16, 2-stage cp.async.
// Epilogue: Q fp32; K and V -> bf16 hi/lo [bgh][i][d] (coalesced u32 stores).
// ---------------------------------------------------------------------------
#define QPITCH 20
#define QSTGF (256 * QPITCH)
#define QSTGB (QSTGF * 4)

__global__ __launch_bounds__(256) void qkv_kernel(const int* __restrict__ idx)
{
    const int cBase = blockIdx.x * 128;
    const int rblk  = blockIdx.y;
    const int b     = rblk >> 5;
    const int jBase = (rblk & 31) * 128;

    __shared__ float sbuf[2][QSTGF];
    __shared__ int   sidx[128];

    const int tid = threadIdx.x;
    const int warp = tid >> 5, lane = tid & 31;
    const int g = lane >> 2, t = lane & 3;
    const int wm = warp >> 1, wn = warp & 1;
    const int mat = lane >> 3, r8 = lane & 7;

    if (tid < 128) sidx[tid] = idx[jBase + tid];
    __syncthreads();

    const float* aG = g_X + ((size_t)b * NN + sidx[tid >> 1]) * CC + (tid & 1) * 8;
    const float* bG = g_Wq + (size_t)(cBase + (tid >> 1)) * CC + (tid & 1) * 8;
    const uint32_t aDst = sptr(&sbuf[0][(tid >> 1) * QPITCH + (tid & 1) * 8]);
    const uint32_t bDst = sptr(&sbuf[0][128 * QPITCH + (tid >> 1) * QPITCH + (tid & 1) * 8]);

    const uint32_t aAddr0 = sptr(&sbuf[0][(wm * 32 + (mat & 1) * 8 + r8) * QPITCH + (mat >> 1) * 4]);
    const uint32_t bAddr0 = sptr(&sbuf[0][128 * QPITCH + (wn * 64 + (mat >> 1) * 8 + r8) * QPITCH + (mat & 1) * 4]);

#define QFILL(st, s) do {                                   \
        cpa16(aDst + (st) * QSTGB,      aG + (s) * 16);     \
        cpa16(aDst + (st) * QSTGB + 16, aG + (s) * 16 + 4); \
        cpa16(bDst + (st) * QSTGB,      bG + (s) * 16);     \
        cpa16(bDst + (st) * QSTGB + 16, bG + (s) * 16 + 4); \
        CP_COMMIT();                                         \
    } while (0)

    float acc[2][8][4] = {};

    QFILL(0, 0);

    for (int s = 0; s < 16; s++) {
        CP_WAIT0();
        __syncthreads();
        if (s < 15) QFILL((s + 1) & 1, s + 1);

        const uint32_t aA = aAddr0 + (s & 1) * QSTGB;
        const uint32_t bA = bAddr0 + (s & 1) * QSTGB;
#pragma unroll
        for (int ks = 0; ks < 2; ks++) {
            uint32_t af[2][4];
#pragma unroll
            for (int mt = 0; mt < 2; mt++)
                ldsm4(aA + (uint32_t)(mt * 16 * QPITCH + ks * 8) * 4,
                      af[mt][0], af[mt][1], af[mt][2], af[mt][3]);
#pragma unroll
            for (int p = 0; p < 4; p++) {
                uint32_t bf[4];
                ldsm4(bA + (uint32_t)(p * 16 * QPITCH + ks * 8) * 4,
                      bf[0], bf[1], bf[2], bf[3]);
                mma8(acc[0][p * 2],     af[0], bf[0], bf[1]);
                mma8(acc[1][p * 2],     af[1], bf[0], bf[1]);
                mma8(acc[0][p * 2 + 1], af[0], bf[2], bf[3]);
                mma8(acc[1][p * 2 + 1], af[1], bf[2], bf[3]);
            }
        }
    }

    // Epilogue
    const int cwb = cBase + wn * 64;
    const int s2 = cwb >> 8;
#pragma unroll
    for (int mt = 0; mt < 2; mt++) {
#pragma unroll
        for (int r = 0; r < 2; r++) {
            int j = jBase + wm * 32 + mt * 16 + g + r * 8;
            int gg = j >> 10, i = j & 1023;
#pragma unroll
            for (int nt = 0; nt < 8; nt++) {
                int c0 = cwb + nt * 8;
                int h = (c0 >> 5) & 7;
                int dd = (c0 & 31) + 2 * t;
                int bgh = (b * GG + gg) * HH + h;
                float v0 = acc[mt][nt][r * 2], v1 = acc[mt][nt][r * 2 + 1];
                size_t off = (size_t)bgh * NG * DD + (size_t)i * DD + dd;
                if (s2 == 0) {
                    *(float2*)&g_Q[off] = make_float2(v0, v1);
                } else {
                    uint32_t hp, lp;
                    splitbf(v0, v1, hp, lp);
                    __nv_bfloat16* dh = (s2 == 1) ? g_Khi : g_Vhi;
                    __nv_bfloat16* dl = (s2 == 1) ? g_Klo : g_Vlo;
                    *(uint32_t*)&dh[off] = hp;
                    *(uint32_t*)&dl[off] = lp;
                }
            }
        }
    }
}

// ---------------------------------------------------------------------------
// Kernel 2: flash attention, static softmax, bf16 3-term mma.
// 512 threads (16 warps, 256 q-rows/CTA) — halves K/V reload traffic.
// V transposed in-register via ldmatrix.trans. grid (4, 128).
// ---------------------------------------------------------------------------
#define KP 40
#define KSTG (64 * KP * 2)

__global__ __launch_bounds__(512) void attn_kernel()
{
    const int bgh = blockIdx.y;

    __shared__ __nv_bfloat16 sKh[2][64][KP];
    __shared__ __nv_bfloat16 sKl[2][64][KP];
    __shared__ __nv_bfloat16 sVh[2][64][KP];
    __shared__ __nv_bfloat16 sVl[2][64][KP];

    const int tid = threadIdx.x;
    const int warp = tid >> 5, lane = tid & 31;
    const int g = lane >> 2, t = lane & 3;
    const int mat = lane >> 3, r8 = lane & 7;
    const int rbase = warp * 16;

    // fill mapping: 512 threads, 2 cpa16 each. tid<256 -> K arrays, else V.
    const int fr = (tid & 255) >> 2;       // row 0..63
    const int fc = (tid & 3) * 8;          // bf16 chunk
    const bool isK = tid < 256;
    const size_t srcOff = (size_t)bgh * NG * DD + fr * 32 + fc;
    const __nv_bfloat16* srcH = (isK ? g_Khi : g_Vhi) + srcOff;
    const __nv_bfloat16* srcL = (isK ? g_Klo : g_Vlo) + srcOff;
    const uint32_t dstH = isK ? sptr(&sKh[0][fr][fc]) : sptr(&sVh[0][fr][fc]);
    const uint32_t dstL = isK ? sptr(&sKl[0][fr][fc]) : sptr(&sVl[0][fr][fc]);

#define ATTN_FILL(buf, kb) do {                                 \
        cpa16(dstH + (buf) * KSTG, srcH + (size_t)(kb) * 2048); \
        cpa16(dstL + (buf) * KSTG, srcL + (size_t)(kb) * 2048); \
    } while (0)

    ATTN_FILL(0, 0);
    CP_COMMIT();

    // K fragments (A-side of S): normal ldmatrix addressing
    const uint32_t kAddrH = sptr(&sKh[0][(mat >> 1) * 8 + r8][(mat & 1) * 8]);
    const uint32_t kAddrL = sptr(&sKl[0][(mat >> 1) * 8 + r8][(mat & 1) * 8]);
    // V fragments (B-side of PV): trans ldmatrix addressing
    const uint32_t vAddrH = sptr(&sVh[0][(mat & 1) * 8 + r8][(mat >> 1) * 8]);
    const uint32_t vAddrL = sptr(&sVl[0][(mat & 1) * 8 + r8][(mat >> 1) * 8]);

    // Q fragments (pre-scaled by SCALE*log2e, bf16 hi/lo), in registers
    uint32_t qh[2][4], ql[2][4];
    {
        const float* Qw = g_Q + (size_t)bgh * NG * DD
                        + (size_t)(blockIdx.x * 256 + rbase) * DD;
#pragma unroll
        for (int s = 0; s < 2; s++) {
            float2 v0 = *(const float2*)&Qw[g * 32 + s * 16 + 2 * t];
            float2 v1 = *(const float2*)&Qw[(g + 8) * 32 + s * 16 + 2 * t];
            float2 v2 = *(const float2*)&Qw[g * 32 + s * 16 + 8 + 2 * t];
            float2 v3 = *(const float2*)&Qw[(g + 8) * 32 + s * 16 + 8 + 2 * t];
            splitbf(v0.x * QSCL, v0.y * QSCL, qh[s][0], ql[s][0]);
            splitbf(v1.x * QSCL, v1.y * QSCL, qh[s][1], ql[s][1]);
            splitbf(v2.x * QSCL, v2.y * QSCL, qh[s][2], ql[s][2]);
            splitbf(v3.x * QSCL, v3.y * QSCL, qh[s][3], ql[s][3]);
        }
    }

    float l0a = 0.f, l1a = 0.f;
    float oc[4][4] = {};

    for (int kb = 0; kb < 16; kb++) {
        const int cur = kb & 1;
        CP_WAIT0();
        __syncthreads();
        if (kb < 15) {
            ATTN_FILL(cur ^ 1, kb + 1);
            CP_COMMIT();
        }

        // --- S = Q K^T (3-term bf16) ---
        float sc[8][4];
#pragma unroll
        for (int nt = 0; nt < 8; nt++)
            sc[nt][0] = sc[nt][1] = sc[nt][2] = sc[nt][3] = 0.f;
#pragma unroll
        for (int s = 0; s < 2; s++) {
#pragma unroll
            for (int p = 0; p < 4; p++) {
                const uint32_t off = cur * KSTG + (uint32_t)(p * 16 * KP + s * 16) * 2;
                uint32_t kh[4], kl[4];
                ldsm4(kAddrH + off, kh[0], kh[1], kh[2], kh[3]);
                ldsm4(kAddrL + off, kl[0], kl[1], kl[2], kl[3]);
                mma16(sc[p * 2],     qh[s], kh[0], kh[1]);
                mma16(sc[p * 2],     qh[s], kl[0], kl[1]);
                mma16(sc[p * 2],     ql[s], kh[0], kh[1]);
                mma16(sc[p * 2 + 1], qh[s], kh[2], kh[3]);
                mma16(sc[p * 2 + 1], qh[s], kl[2], kl[3]);
                mma16(sc[p * 2 + 1], ql[s], kh[2], kh[3]);
            }
        }

        // --- static softmax: p = 2^sc, local l accumulation only ---
#pragma unroll
        for (int nt = 0; nt < 8; nt++) {
            sc[nt][0] = ex2(sc[nt][0]); l0a += sc[nt][0];
            sc[nt][1] = ex2(sc[nt][1]); l0a += sc[nt][1];
            sc[nt][2] = ex2(sc[nt][2]); l1a += sc[nt][2];
            sc[nt][3] = ex2(sc[nt][3]); l1a += sc[nt][3];
        }

        // --- O += P @ V (3-term bf16; V transposed via ldmatrix.trans) ---
#pragma unroll
        for (int s = 0; s < 4; s++) {
            uint32_t ah[4], al[4];
            splitbf(sc[2 * s][0],     sc[2 * s][1],     ah[0], al[0]);
            splitbf(sc[2 * s][2],     sc[2 * s][3],     ah[1], al[1]);
            splitbf(sc[2 * s + 1][0], sc[2 * s + 1][1], ah[2], al[2]);
            splitbf(sc[2 * s + 1][2], sc[2 * s + 1][3], ah[3], al[3]);
            const uint32_t off = cur * KSTG + (uint32_t)(s * 16 * KP) * 2;
            uint32_t vh[4], vl[4];
            ldsm4t(vAddrH + off, vh[0], vh[1], vh[2], vh[3]);
            ldsm4t(vAddrL + off, vl[0], vl[1], vl[2], vl[3]);
            mma16(oc[0], ah, vh[0], vh[1]);
            mma16(oc[0], ah, vl[0], vl[1]);
            mma16(oc[0], al, vh[0], vh[1]);
            mma16(oc[1], ah, vh[2], vh[3]);
            mma16(oc[1], ah, vl[2], vl[3]);
            mma16(oc[1], al, vh[2], vh[3]);
            const uint32_t off2 = off + 16 * 2;   // d block 16..31
            ldsm4t(vAddrH + off2, vh[0], vh[1], vh[2], vh[3]);
            ldsm4t(vAddrL + off2, vl[0], vl[1], vl[2], vl[3]);
            mma16(oc[2], ah, vh[0], vh[1]);
            mma16(oc[2], ah, vl[0], vl[1]);
            mma16(oc[2], al, vh[0], vh[1]);
            mma16(oc[3], ah, vh[2], vh[3]);
            mma16(oc[3], ah, vl[2], vl[3]);
            mma16(oc[3], al, vh[2], vh[3]);
        }
    }

    // l reduction (once) + finalize (tf32 bits, ready for proj's A operand)
    l0a += __shfl_xor_sync(0xffffffffu, l0a, 1);
    l0a += __shfl_xor_sync(0xffffffffu, l0a, 2);
    l1a += __shfl_xor_sync(0xffffffffu, l1a, 1);
    l1a += __shfl_xor_sync(0xffffffffu, l1a, 2);

    const int b = bgh >> 5, gg = (bgh >> 3) & 3, h = bgh & 7;
    float inv0 = 1.f / l0a, inv1 = 1.f / l1a;
    int i0 = blockIdx.x * 256 + rbase + g;
    size_t row0 = ((size_t)b * NN + (size_t)gg * NG + i0) * CC + h * DD;
    size_t row1 = row0 + (size_t)8 * CC;
#pragma unroll
    for (int nt = 0; nt < 4; nt++) {
        *(float2*)&g_O[row0 + nt * 8 + 2 * t] =
            make_float2(__uint_as_float(to_tf32(oc[nt][0] * inv0)),
                        __uint_as_float(to_tf32(oc[nt][1] * inv0)));
        *(float2*)&g_O[row1 + nt * 8 + 2 * t] =
            make_float2(__uint_as_float(to_tf32(oc[nt][2] * inv1)),
                        __uint_as_float(to_tf32(oc[nt][3] * inv1)));
    }
}

// ---------------------------------------------------------------------------
// Kernel 3: out[b, idx[j], :] = g_O[b, j, :] @ g_Wp^T + bias
// 128x128 tile (same structure as qkv), grid (2, 128), 256 thr.
// ---------------------------------------------------------------------------
__global__ __launch_bounds__(256) void proj_kernel(
    const int* __restrict__ idx, const float* __restrict__ bias,
    float* __restrict__ out)
{
    const int cBase = blockIdx.x * 128;
    const int rblk  = blockIdx.y;
    const int b     = rblk >> 5;
    const int jBase = (rblk & 31) * 128;

    __shared__ float sbuf[2][QSTGF];
    __shared__ int   sidx[128];

    const int tid = threadIdx.x;
    const int warp = tid >> 5, lane = tid & 31;
    const int g = lane >> 2, t = lane & 3;
    const int wm = warp >> 1, wn = warp & 1;
    const int mat = lane >> 3, r8 = lane & 7;

    if (tid < 128) sidx[tid] = idx[jBase + tid];
    __syncthreads();

    const float* aG = g_O + ((size_t)b * NN + jBase + (tid >> 1)) * CC + (tid & 1) * 8;
    const float* bG = g_Wp + (size_t)(cBase + (tid >> 1)) * CC + (tid & 1) * 8;
    const uint32_t aDst = sptr(&sbuf[0][(tid >> 1) * QPITCH + (tid & 1) * 8]);
    const uint32_t bDst = sptr(&sbuf[0][128 * QPITCH + (tid >> 1) * QPITCH + (tid & 1) * 8]);

    const uint32_t aAddr0 = sptr(&sbuf[0][(wm * 32 + (mat & 1) * 8 + r8) * QPITCH + (mat >> 1) * 4]);
    const uint32_t bAddr0 = sptr(&sbuf[0][128 * QPITCH + (wn * 64 + (mat >> 1) * 8 + r8) * QPITCH + (mat & 1) * 4]);

    float acc[2][8][4] = {};

    QFILL(0, 0);

    for (int s = 0; s < 16; s++) {
        CP_WAIT0();
        __syncthreads();
        if (s < 15) QFILL((s + 1) & 1, s + 1);

        const uint32_t aA = aAddr0 + (s & 1) * QSTGB;
        const uint32_t bA = bAddr0 + (s & 1) * QSTGB;
#pragma unroll
        for (int ks = 0; ks < 2; ks++) {
            uint32_t af[2][4];
#pragma unroll
            for (int mt = 0; mt < 2; mt++)
                ldsm4(aA + (uint32_t)(mt * 16 * QPITCH + ks * 8) * 4,
                      af[mt][0], af[mt][1], af[mt][2], af[mt][3]);
#pragma unroll
            for (int p = 0; p < 4; p++) {
                uint32_t bf[4];
                ldsm4(bA + (uint32_t)(p * 16 * QPITCH + ks * 8) * 4,
                      bf[0], bf[1], bf[2], bf[3]);
                mma8(acc[0][p * 2],     af[0], bf[0], bf[1]);
                mma8(acc[1][p * 2],     af[1], bf[0], bf[1]);
                mma8(acc[0][p * 2 + 1], af[0], bf[2], bf[3]);
                mma8(acc[1][p * 2 + 1], af[1], bf[2], bf[3]);
            }
        }
    }

    // Epilogue: bias + inverse-permutation row scatter
    const int cwb = cBase + wn * 64;
    float2 bb[8];
#pragma unroll
    for (int nt = 0; nt < 8; nt++)
        bb[nt] = *(const float2*)&bias[cwb + nt * 8 + 2 * t];

#pragma unroll
    for (int mt = 0; mt < 2; mt++) {
#pragma unroll
        for (int r = 0; r < 2; r++) {
            int jl = wm * 32 + mt * 16 + g + r * 8;
            int orow = sidx[jl];
            size_t base = ((size_t)b * NN + orow) * CC + cwb;
#pragma unroll
            for (int nt = 0; nt < 8; nt++) {
                *(float2*)&out[base + nt * 8 + 2 * t] =
                    make_float2(acc[mt][nt][r * 2] + bb[nt].x,
                                acc[mt][nt][r * 2 + 1] + bb[nt].y);
            }
        }
    }
}

// ---------------------------------------------------------------------------
extern "C" void kernel_launch(void* const* d_in, const int* in_sizes, int n_in,
                              void* d_out, int out_size)
{
    (void)in_sizes; (void)n_in; (void)out_size;
    const float* x      = (const float*)d_in[0];
    const int*   idx    = (const int*)d_in[1];
    const float* w_qkv  = (const float*)d_in[2];
    const float* w_proj = (const float*)d_in[3];
    const float* b_proj = (const float*)d_in[4];
    float* out = (float*)d_out;

    prep_kernel<<<(XTOT + WQTOT + WPTOT) / 4 / 256, 256>>>(x, w_qkv, w_proj);
    qkv_kernel<<<dim3(6, 128), 256>>>(idx);
    attn_kernel<<<dim3(4, 128), 512>>>();
    proj_kernel<<<dim3(2, 128), 256>>>(idx, b_proj, out);
}

// round 13
// speedup vs baseline: 1.0792x; 1.0792x over previous
#include <cuda_runtime.h>
#include <cuda_bf16.h>
#include <math.h>
#include <stdint.h>

// Problem constants
#define BB 4
#define NN 4096
#define CC 256
#define HH 8
#define GG 4
#define DD 32
#define NG 1024
#define QSCL (0.17677669529663687f * 1.4426950408889634f)  // 1/sqrt(32)*log2(e)

#define XTOT  (BB * NN * CC)
#define WQTOT (3 * CC * CC)
#define WPTOT (CC * CC)

// Scratch (device globals; allocation-free)
__device__ float g_X[XTOT];
__device__ float g_Wq[WQTOT];
__device__ float g_Wp[WPTOT];
__device__ float g_Q[BB * GG * HH * NG * DD];
__device__ __nv_bfloat16 g_Khi[BB * GG * HH * NG * DD];   // [bgh][i][d]
__device__ __nv_bfloat16 g_Klo[BB * GG * HH * NG * DD];
__device__ __nv_bfloat16 g_Vhi[BB * GG * HH * NG * DD];   // [bgh][i][d]
__device__ __nv_bfloat16 g_Vlo[BB * GG * HH * NG * DD];
__device__ float g_O[BB * NN * CC];                        // tf32 bits

// ---------------------------------------------------------------------------
// PTX helpers
// ---------------------------------------------------------------------------
__device__ __forceinline__ void mma8(float c[4], const uint32_t a[4],
                                     uint32_t b0, uint32_t b1) {
    asm volatile(
        "mma.sync.aligned.m16n8k8.row.col.f32.tf32.tf32.f32 "
        "{%0,%1,%2,%3}, {%4,%5,%6,%7}, {%8,%9}, {%0,%1,%2,%3};"
        : "+f"(c[0]), "+f"(c[1]), "+f"(c[2]), "+f"(c[3])
        : "r"(a[0]), "r"(a[1]), "r"(a[2]), "r"(a[3]), "r"(b0), "r"(b1));
}
__device__ __forceinline__ void mma16(float c[4], const uint32_t a[4],
                                      uint32_t b0, uint32_t b1) {
    asm volatile(
        "mma.sync.aligned.m16n8k16.row.col.f32.bf16.bf16.f32 "
        "{%0,%1,%2,%3}, {%4,%5,%6,%7}, {%8,%9}, {%0,%1,%2,%3};"
        : "+f"(c[0]), "+f"(c[1]), "+f"(c[2]), "+f"(c[3])
        : "r"(a[0]), "r"(a[1]), "r"(a[2]), "r"(a[3]), "r"(b0), "r"(b1));
}
__device__ __forceinline__ uint32_t to_tf32(float x) {
    uint32_t h; asm("cvt.rna.tf32.f32 %0, %1;" : "=r"(h) : "f"(x)); return h;
}
__device__ __forceinline__ float ex2(float x) {
    float r; asm("ex2.approx.ftz.f32 %0, %1;" : "=f"(r) : "f"(x)); return r;
}
__device__ __forceinline__ uint32_t packbf(float x, float y) {
    uint32_t r; asm("cvt.rn.bf16x2.f32 %0, %1, %2;" : "=r"(r) : "f"(y), "f"(x));
    return r;
}
__device__ __forceinline__ void splitbf(float x, float y, uint32_t& h, uint32_t& l) {
    h = packbf(x, y);
    __nv_bfloat162 hb = *reinterpret_cast<__nv_bfloat162*>(&h);
    l = packbf(x - __bfloat162float(hb.x), y - __bfloat162float(hb.y));
}
__device__ __forceinline__ uint32_t sptr(const void* p) {
    return (uint32_t)__cvta_generic_to_shared(p);
}
__device__ __forceinline__ void ldsm4(uint32_t addr, uint32_t& r0, uint32_t& r1,
                                      uint32_t& r2, uint32_t& r3) {
    asm volatile("ldmatrix.sync.aligned.m8n8.x4.shared.b16 {%0,%1,%2,%3}, [%4];"
                 : "=r"(r0), "=r"(r1), "=r"(r2), "=r"(r3) : "r"(addr));
}
__device__ __forceinline__ void ldsm4t(uint32_t addr, uint32_t& r0, uint32_t& r1,
                                       uint32_t& r2, uint32_t& r3) {
    asm volatile("ldmatrix.sync.aligned.m8n8.x4.trans.shared.b16 {%0,%1,%2,%3}, [%4];"
                 : "=r"(r0), "=r"(r1), "=r"(r2), "=r"(r3) : "r"(addr));
}
__device__ __forceinline__ void cpa16(uint32_t dst, const void* src) {
    asm volatile("cp.async.cg.shared.global [%0], [%1], 16;" :: "r"(dst), "l"(src));
}
#define CP_COMMIT() asm volatile("cp.async.commit_group;")
#define CP_WAIT0()  asm volatile("cp.async.wait_group 0;")

// ---------------------------------------------------------------------------
// Kernel 0: pre-convert x, w_qkv, w_proj to tf32 bit patterns
// ---------------------------------------------------------------------------
__global__ __launch_bounds__(256) void prep_kernel(
    const float* __restrict__ x, const float* __restrict__ wq,
    const float* __restrict__ wp)
{
    int i = blockIdx.x * 256 + threadIdx.x;
    const float4* src; float4* dst; int off;
    if (i < XTOT / 4)                { src = (const float4*)x;  dst = (float4*)g_X;  off = i; }
    else if (i < (XTOT + WQTOT) / 4) { src = (const float4*)wq; dst = (float4*)g_Wq; off = i - XTOT / 4; }
    else                             { src = (const float4*)wp; dst = (float4*)g_Wp; off = i - (XTOT + WQTOT) / 4; }
    float4 v = src[off];
    v.x = __uint_as_float(to_tf32(v.x));
    v.y = __uint_as_float(to_tf32(v.y));
    v.z = __uint_as_float(to_tf32(v.z));
    v.w = __uint_as_float(to_tf32(v.w));
    dst[off] = v;
}

// ---------------------------------------------------------------------------
// Kernel 1: QKV = gather(g_X, idx) @ g_Wq^T  (tf32 mma, 128x128 tile)
// 8 warps (4m x 2n), warp tile 32x64, k-slab 16, 2-stage cp.async.
// Epilogue: Q fp32; K and V -> bf16 hi/lo [bgh][i][d] (coalesced u32 stores).
// ---------------------------------------------------------------------------
#define QPITCH 20
#define QSTGF (256 * QPITCH)
#define QSTGB (QSTGF * 4)

__global__ __launch_bounds__(256) void qkv_kernel(const int* __restrict__ idx)
{
    const int cBase = blockIdx.x * 128;
    const int rblk  = blockIdx.y;
    const int b     = rblk >> 5;
    const int jBase = (rblk & 31) * 128;

    __shared__ float sbuf[2][QSTGF];
    __shared__ int   sidx[128];

    const int tid = threadIdx.x;
    const int warp = tid >> 5, lane = tid & 31;
    const int g = lane >> 2, t = lane & 3;
    const int wm = warp >> 1, wn = warp & 1;
    const int mat = lane >> 3, r8 = lane & 7;

    if (tid < 128) sidx[tid] = idx[jBase + tid];
    __syncthreads();

    const float* aG = g_X + ((size_t)b * NN + sidx[tid >> 1]) * CC + (tid & 1) * 8;
    const float* bG = g_Wq + (size_t)(cBase + (tid >> 1)) * CC + (tid & 1) * 8;
    const uint32_t aDst = sptr(&sbuf[0][(tid >> 1) * QPITCH + (tid & 1) * 8]);
    const uint32_t bDst = sptr(&sbuf[0][128 * QPITCH + (tid >> 1) * QPITCH + (tid & 1) * 8]);

    const uint32_t aAddr0 = sptr(&sbuf[0][(wm * 32 + (mat & 1) * 8 + r8) * QPITCH + (mat >> 1) * 4]);
    const uint32_t bAddr0 = sptr(&sbuf[0][128 * QPITCH + (wn * 64 + (mat >> 1) * 8 + r8) * QPITCH + (mat & 1) * 4]);

#define QFILL(st, s) do {                                   \
        cpa16(aDst + (st) * QSTGB,      aG + (s) * 16);     \
        cpa16(aDst + (st) * QSTGB + 16, aG + (s) * 16 + 4); \
        cpa16(bDst + (st) * QSTGB,      bG + (s) * 16);     \
        cpa16(bDst + (st) * QSTGB + 16, bG + (s) * 16 + 4); \
        CP_COMMIT();                                         \
    } while (0)

    float acc[2][8][4] = {};

    QFILL(0, 0);

    for (int s = 0; s < 16; s++) {
        CP_WAIT0();
        __syncthreads();
        if (s < 15) QFILL((s + 1) & 1, s + 1);

        const uint32_t aA = aAddr0 + (s & 1) * QSTGB;
        const uint32_t bA = bAddr0 + (s & 1) * QSTGB;
#pragma unroll
        for (int ks = 0; ks < 2; ks++) {
            uint32_t af[2][4];
#pragma unroll
            for (int mt = 0; mt < 2; mt++)
                ldsm4(aA + (uint32_t)(mt * 16 * QPITCH + ks * 8) * 4,
                      af[mt][0], af[mt][1], af[mt][2], af[mt][3]);
#pragma unroll
            for (int p = 0; p < 4; p++) {
                uint32_t bf[4];
                ldsm4(bA + (uint32_t)(p * 16 * QPITCH + ks * 8) * 4,
                      bf[0], bf[1], bf[2], bf[3]);
                mma8(acc[0][p * 2],     af[0], bf[0], bf[1]);
                mma8(acc[1][p * 2],     af[1], bf[0], bf[1]);
                mma8(acc[0][p * 2 + 1], af[0], bf[2], bf[3]);
                mma8(acc[1][p * 2 + 1], af[1], bf[2], bf[3]);
            }
        }
    }

    // Epilogue
    const int cwb = cBase + wn * 64;
    const int s2 = cwb >> 8;
#pragma unroll
    for (int mt = 0; mt < 2; mt++) {
#pragma unroll
        for (int r = 0; r < 2; r++) {
            int j = jBase + wm * 32 + mt * 16 + g + r * 8;
            int gg = j >> 10, i = j & 1023;
#pragma unroll
            for (int nt = 0; nt < 8; nt++) {
                int c0 = cwb + nt * 8;
                int h = (c0 >> 5) & 7;
                int dd = (c0 & 31) + 2 * t;
                int bgh = (b * GG + gg) * HH + h;
                float v0 = acc[mt][nt][r * 2], v1 = acc[mt][nt][r * 2 + 1];
                size_t off = (size_t)bgh * NG * DD + (size_t)i * DD + dd;
                if (s2 == 0) {
                    *(float2*)&g_Q[off] = make_float2(v0, v1);
                } else {
                    uint32_t hp, lp;
                    splitbf(v0, v1, hp, lp);
                    __nv_bfloat16* dh = (s2 == 1) ? g_Khi : g_Vhi;
                    __nv_bfloat16* dl = (s2 == 1) ? g_Klo : g_Vlo;
                    *(uint32_t*)&dh[off] = hp;
                    *(uint32_t*)&dl[off] = lp;
                }
            }
        }
    }
}

// ---------------------------------------------------------------------------
// Kernel 2: flash attention, static softmax, bf16 3-term mma (R9 config).
// 256 threads (8 warps, 128 q-rows/CTA), grid (8, 128).
// V transposed in-register via ldmatrix.trans.
// ---------------------------------------------------------------------------
#define KP 40
#define KSTG (64 * KP * 2)

__global__ __launch_bounds__(256) void attn_kernel()
{
    const int bgh = blockIdx.y;

    __shared__ __nv_bfloat16 sKh[2][64][KP];
    __shared__ __nv_bfloat16 sKl[2][64][KP];
    __shared__ __nv_bfloat16 sVh[2][64][KP];
    __shared__ __nv_bfloat16 sVl[2][64][KP];

    const int tid = threadIdx.x;
    const int warp = tid >> 5, lane = tid & 31;
    const int g = lane >> 2, t = lane & 3;
    const int mat = lane >> 3, r8 = lane & 7;
    const int rbase = warp * 16;

    const size_t srcOff = (size_t)bgh * NG * DD + (tid >> 2) * 32 + (tid & 3) * 8;
    const __nv_bfloat16* kSrcH = g_Khi + srcOff;
    const __nv_bfloat16* kSrcL = g_Klo + srcOff;
    const __nv_bfloat16* vSrcH = g_Vhi + srcOff;
    const __nv_bfloat16* vSrcL = g_Vlo + srcOff;
    const uint32_t kDstH = sptr(&sKh[0][tid >> 2][(tid & 3) * 8]);
    const uint32_t kDstL = sptr(&sKl[0][tid >> 2][(tid & 3) * 8]);
    const uint32_t vDstH = sptr(&sVh[0][tid >> 2][(tid & 3) * 8]);
    const uint32_t vDstL = sptr(&sVl[0][tid >> 2][(tid & 3) * 8]);

#define ATTN_FILL(buf, kb) do {                                   \
        cpa16(kDstH + (buf) * KSTG, kSrcH + (size_t)(kb) * 2048); \
        cpa16(kDstL + (buf) * KSTG, kSrcL + (size_t)(kb) * 2048); \
        cpa16(vDstH + (buf) * KSTG, vSrcH + (size_t)(kb) * 2048); \
        cpa16(vDstL + (buf) * KSTG, vSrcL + (size_t)(kb) * 2048); \
    } while (0)

    ATTN_FILL(0, 0);
    CP_COMMIT();

    const uint32_t kAddrH = sptr(&sKh[0][(mat >> 1) * 8 + r8][(mat & 1) * 8]);
    const uint32_t kAddrL = sptr(&sKl[0][(mat >> 1) * 8 + r8][(mat & 1) * 8]);
    const uint32_t vAddrH = sptr(&sVh[0][(mat & 1) * 8 + r8][(mat >> 1) * 8]);
    const uint32_t vAddrL = sptr(&sVl[0][(mat & 1) * 8 + r8][(mat >> 1) * 8]);

    uint32_t qh[2][4], ql[2][4];
    {
        const float* Qw = g_Q + (size_t)bgh * NG * DD
                        + (size_t)(blockIdx.x * 128 + rbase) * DD;
#pragma unroll
        for (int s = 0; s < 2; s++) {
            float2 v0 = *(const float2*)&Qw[g * 32 + s * 16 + 2 * t];
            float2 v1 = *(const float2*)&Qw[(g + 8) * 32 + s * 16 + 2 * t];
            float2 v2 = *(const float2*)&Qw[g * 32 + s * 16 + 8 + 2 * t];
            float2 v3 = *(const float2*)&Qw[(g + 8) * 32 + s * 16 + 8 + 2 * t];
            splitbf(v0.x * QSCL, v0.y * QSCL, qh[s][0], ql[s][0]);
            splitbf(v1.x * QSCL, v1.y * QSCL, qh[s][1], ql[s][1]);
            splitbf(v2.x * QSCL, v2.y * QSCL, qh[s][2], ql[s][2]);
            splitbf(v3.x * QSCL, v3.y * QSCL, qh[s][3], ql[s][3]);
        }
    }

    float l0a = 0.f, l1a = 0.f;
    float oc[4][4] = {};

    for (int kb = 0; kb < 16; kb++) {
        const int cur = kb & 1;
        CP_WAIT0();
        __syncthreads();
        if (kb < 15) {
            ATTN_FILL(cur ^ 1, kb + 1);
            CP_COMMIT();
        }

        // --- S = Q K^T (3-term bf16) ---
        float sc[8][4];
#pragma unroll
        for (int nt = 0; nt < 8; nt++)
            sc[nt][0] = sc[nt][1] = sc[nt][2] = sc[nt][3] = 0.f;
#pragma unroll
        for (int s = 0; s < 2; s++) {
#pragma unroll
            for (int p = 0; p < 4; p++) {
                const uint32_t off = cur * KSTG + (uint32_t)(p * 16 * KP + s * 16) * 2;
                uint32_t kh[4], kl[4];
                ldsm4(kAddrH + off, kh[0], kh[1], kh[2], kh[3]);
                ldsm4(kAddrL + off, kl[0], kl[1], kl[2], kl[3]);
                mma16(sc[p * 2],     qh[s], kh[0], kh[1]);
                mma16(sc[p * 2],     qh[s], kl[0], kl[1]);
                mma16(sc[p * 2],     ql[s], kh[0], kh[1]);
                mma16(sc[p * 2 + 1], qh[s], kh[2], kh[3]);
                mma16(sc[p * 2 + 1], qh[s], kl[2], kl[3]);
                mma16(sc[p * 2 + 1], ql[s], kh[2], kh[3]);
            }
        }

        // --- static softmax: p = 2^sc, local l accumulation only ---
#pragma unroll
        for (int nt = 0; nt < 8; nt++) {
            sc[nt][0] = ex2(sc[nt][0]); l0a += sc[nt][0];
            sc[nt][1] = ex2(sc[nt][1]); l0a += sc[nt][1];
            sc[nt][2] = ex2(sc[nt][2]); l1a += sc[nt][2];
            sc[nt][3] = ex2(sc[nt][3]); l1a += sc[nt][3];
        }

        // --- O += P @ V (3-term bf16; V transposed via ldmatrix.trans) ---
#pragma unroll
        for (int s = 0; s < 4; s++) {
            uint32_t ah[4], al[4];
            splitbf(sc[2 * s][0],     sc[2 * s][1],     ah[0], al[0]);
            splitbf(sc[2 * s][2],     sc[2 * s][3],     ah[1], al[1]);
            splitbf(sc[2 * s + 1][0], sc[2 * s + 1][1], ah[2], al[2]);
            splitbf(sc[2 * s + 1][2], sc[2 * s + 1][3], ah[3], al[3]);
            const uint32_t off = cur * KSTG + (uint32_t)(s * 16 * KP) * 2;
            uint32_t vh[4], vl[4];
            ldsm4t(vAddrH + off, vh[0], vh[1], vh[2], vh[3]);
            ldsm4t(vAddrL + off, vl[0], vl[1], vl[2], vl[3]);
            mma16(oc[0], ah, vh[0], vh[1]);
            mma16(oc[0], ah, vl[0], vl[1]);
            mma16(oc[0], al, vh[0], vh[1]);
            mma16(oc[1], ah, vh[2], vh[3]);
            mma16(oc[1], ah, vl[2], vl[3]);
            mma16(oc[1], al, vh[2], vh[3]);
            const uint32_t off2 = off + 16 * 2;
            ldsm4t(vAddrH + off2, vh[0], vh[1], vh[2], vh[3]);
            ldsm4t(vAddrL + off2, vl[0], vl[1], vl[2], vl[3]);
            mma16(oc[2], ah, vh[0], vh[1]);
            mma16(oc[2], ah, vl[0], vl[1]);
            mma16(oc[2], al, vh[0], vh[1]);
            mma16(oc[3], ah, vh[2], vh[3]);
            mma16(oc[3], ah, vl[2], vl[3]);
            mma16(oc[3], al, vh[2], vh[3]);
        }
    }

    l0a += __shfl_xor_sync(0xffffffffu, l0a, 1);
    l0a += __shfl_xor_sync(0xffffffffu, l0a, 2);
    l1a += __shfl_xor_sync(0xffffffffu, l1a, 1);
    l1a += __shfl_xor_sync(0xffffffffu, l1a, 2);

    const int b = bgh >> 5, gg = (bgh >> 3) & 3, h = bgh & 7;
    float inv0 = 1.f / l0a, inv1 = 1.f / l1a;
    int i0 = blockIdx.x * 128 + rbase + g;
    size_t row0 = ((size_t)b * NN + (size_t)gg * NG + i0) * CC + h * DD;
    size_t row1 = row0 + (size_t)8 * CC;
#pragma unroll
    for (int nt = 0; nt < 4; nt++) {
        *(float2*)&g_O[row0 + nt * 8 + 2 * t] =
            make_float2(__uint_as_float(to_tf32(oc[nt][0] * inv0)),
                        __uint_as_float(to_tf32(oc[nt][1] * inv0)));
        *(float2*)&g_O[row1 + nt * 8 + 2 * t] =
            make_float2(__uint_as_float(to_tf32(oc[nt][2] * inv1)),
                        __uint_as_float(to_tf32(oc[nt][3] * inv1)));
    }
}

// ---------------------------------------------------------------------------
// Kernel 3: out[b, idx[j], :] = g_O[b, j, :] @ g_Wp^T + bias
// 128x128 tile (same structure as qkv), grid (2, 128), 256 thr.
// ---------------------------------------------------------------------------
__global__ __launch_bounds__(256) void proj_kernel(
    const int* __restrict__ idx, const float* __restrict__ bias,
    float* __restrict__ out)
{
    const int cBase = blockIdx.x * 128;
    const int rblk  = blockIdx.y;
    const int b     = rblk >> 5;
    const int jBase = (rblk & 31) * 128;

    __shared__ float sbuf[2][QSTGF];
    __shared__ int   sidx[128];

    const int tid = threadIdx.x;
    const int warp = tid >> 5, lane = tid & 31;
    const int g = lane >> 2, t = lane & 3;
    const int wm = warp >> 1, wn = warp & 1;
    const int mat = lane >> 3, r8 = lane & 7;

    if (tid < 128) sidx[tid] = idx[jBase + tid];
    __syncthreads();

    const float* aG = g_O + ((size_t)b * NN + jBase + (tid >> 1)) * CC + (tid & 1) * 8;
    const float* bG = g_Wp + (size_t)(cBase + (tid >> 1)) * CC + (tid & 1) * 8;
    const uint32_t aDst = sptr(&sbuf[0][(tid >> 1) * QPITCH + (tid & 1) * 8]);
    const uint32_t bDst = sptr(&sbuf[0][128 * QPITCH + (tid >> 1) * QPITCH + (tid & 1) * 8]);

    const uint32_t aAddr0 = sptr(&sbuf[0][(wm * 32 + (mat & 1) * 8 + r8) * QPITCH + (mat >> 1) * 4]);
    const uint32_t bAddr0 = sptr(&sbuf[0][128 * QPITCH + (wn * 64 + (mat >> 1) * 8 + r8) * QPITCH + (mat & 1) * 4]);

    float acc[2][8][4] = {};

    QFILL(0, 0);

    for (int s = 0; s < 16; s++) {
        CP_WAIT0();
        __syncthreads();
        if (s < 15) QFILL((s + 1) & 1, s + 1);

        const uint32_t aA = aAddr0 + (s & 1) * QSTGB;
        const uint32_t bA = bAddr0 + (s & 1) * QSTGB;
#pragma unroll
        for (int ks = 0; ks < 2; ks++) {
            uint32_t af[2][4];
#pragma unroll
            for (int mt = 0; mt < 2; mt++)
                ldsm4(aA + (uint32_t)(mt * 16 * QPITCH + ks * 8) * 4,
                      af[mt][0], af[mt][1], af[mt][2], af[mt][3]);
#pragma unroll
            for (int p = 0; p < 4; p++) {
                uint32_t bf[4];
                ldsm4(bA + (uint32_t)(p * 16 * QPITCH + ks * 8) * 4,
                      bf[0], bf[1], bf[2], bf[3]);
                mma8(acc[0][p * 2],     af[0], bf[0], bf[1]);
                mma8(acc[1][p * 2],     af[1], bf[0], bf[1]);
                mma8(acc[0][p * 2 + 1], af[0], bf[2], bf[3]);
                mma8(acc[1][p * 2 + 1], af[1], bf[2], bf[3]);
            }
        }
    }

    // Epilogue: bias + inverse-permutation row scatter
    const int cwb = cBase + wn * 64;
    float2 bb[8];
#pragma unroll
    for (int nt = 0; nt < 8; nt++)
        bb[nt] = *(const float2*)&bias[cwb + nt * 8 + 2 * t];

#pragma unroll
    for (int mt = 0; mt < 2; mt++) {
#pragma unroll
        for (int r = 0; r < 2; r++) {
            int jl = wm * 32 + mt * 16 + g + r * 8;
            int orow = sidx[jl];
            size_t base = ((size_t)b * NN + orow) * CC + cwb;
#pragma unroll
            for (int nt = 0; nt < 8; nt++) {
                *(float2*)&out[base + nt * 8 + 2 * t] =
                    make_float2(acc[mt][nt][r * 2] + bb[nt].x,
                                acc[mt][nt][r * 2 + 1] + bb[nt].y);
            }
        }
    }
}

// ---------------------------------------------------------------------------
extern "C" void kernel_launch(void* const* d_in, const int* in_sizes, int n_in,
                              void* d_out, int out_size)
{
    (void)in_sizes; (void)n_in; (void)out_size;
    const float* x      = (const float*)d_in[0];
    const int*   idx    = (const int*)d_in[1];
    const float* w_qkv  = (const float*)d_in[2];
    const float* w_proj = (const float*)d_in[3];
    const float* b_proj = (const float*)d_in[4];
    float* out = (float*)d_out;

    prep_kernel<<<(XTOT + WQTOT + WPTOT) / 4 / 256, 256>>>(x, w_qkv, w_proj);
    qkv_kernel<<<dim3(6, 128), 256>>>(idx);
    attn_kernel<<<dim3(8, 128), 256>>>();
    proj_kernel<<<dim3(2, 128), 256>>>(idx, b_proj, out);
}

// round 14
// speedup vs baseline: 1.2107x; 1.1218x over previous
#include <cuda_runtime.h>
#include <cuda_bf16.h>
#include <cuda_fp16.h>
#include <math.h>
#include <stdint.h>

// Problem constants
#define BB 4
#define NN 4096
#define CC 256
#define HH 8
#define GG 4
#define DD 32
#define NG 1024
#define QSCL (0.17677669529663687f * 1.4426950408889634f)  // 1/sqrt(32)*log2(e)

#define XTOT  (BB * NN * CC)
#define WQTOT (3 * CC * CC)
#define WPTOT (CC * CC)

// Scratch (device globals; allocation-free)
__device__ float g_X[XTOT];
__device__ float g_Wq[WQTOT];
__device__ float g_Wp[WPTOT];
__device__ float g_Q[BB * GG * HH * NG * DD];
__device__ __nv_bfloat16 g_Khi[BB * GG * HH * NG * DD];   // [bgh][i][d]
__device__ __nv_bfloat16 g_Klo[BB * GG * HH * NG * DD];
__device__ __half g_Vhi[BB * GG * HH * NG * DD];          // [bgh][i][d] fp16
__device__ __half g_Vlo[BB * GG * HH * NG * DD];
__device__ float g_O[BB * NN * CC];                        // tf32 bits

// ---------------------------------------------------------------------------
// PTX helpers
// ---------------------------------------------------------------------------
__device__ __forceinline__ void mma8(float c[4], const uint32_t a[4],
                                     uint32_t b0, uint32_t b1) {
    asm volatile(
        "mma.sync.aligned.m16n8k8.row.col.f32.tf32.tf32.f32 "
        "{%0,%1,%2,%3}, {%4,%5,%6,%7}, {%8,%9}, {%0,%1,%2,%3};"
        : "+f"(c[0]), "+f"(c[1]), "+f"(c[2]), "+f"(c[3])
        : "r"(a[0]), "r"(a[1]), "r"(a[2]), "r"(a[3]), "r"(b0), "r"(b1));
}
__device__ __forceinline__ void mma16(float c[4], const uint32_t a[4],
                                      uint32_t b0, uint32_t b1) {
    asm volatile(
        "mma.sync.aligned.m16n8k16.row.col.f32.bf16.bf16.f32 "
        "{%0,%1,%2,%3}, {%4,%5,%6,%7}, {%8,%9}, {%0,%1,%2,%3};"
        : "+f"(c[0]), "+f"(c[1]), "+f"(c[2]), "+f"(c[3])
        : "r"(a[0]), "r"(a[1]), "r"(a[2]), "r"(a[3]), "r"(b0), "r"(b1));
}
__device__ __forceinline__ void mma16h(float c[4], const uint32_t a[4],
                                       uint32_t b0, uint32_t b1) {
    asm volatile(
        "mma.sync.aligned.m16n8k16.row.col.f32.f16.f16.f32 "
        "{%0,%1,%2,%3}, {%4,%5,%6,%7}, {%8,%9}, {%0,%1,%2,%3};"
        : "+f"(c[0]), "+f"(c[1]), "+f"(c[2]), "+f"(c[3])
        : "r"(a[0]), "r"(a[1]), "r"(a[2]), "r"(a[3]), "r"(b0), "r"(b1));
}
__device__ __forceinline__ uint32_t to_tf32(float x) {
    uint32_t h; asm("cvt.rna.tf32.f32 %0, %1;" : "=r"(h) : "f"(x)); return h;
}
__device__ __forceinline__ float ex2(float x) {
    float r; asm("ex2.approx.ftz.f32 %0, %1;" : "=f"(r) : "f"(x)); return r;
}
__device__ __forceinline__ uint32_t packbf(float x, float y) {
    uint32_t r; asm("cvt.rn.bf16x2.f32 %0, %1, %2;" : "=r"(r) : "f"(y), "f"(x));
    return r;
}
__device__ __forceinline__ void splitbf(float x, float y, uint32_t& h, uint32_t& l) {
    h = packbf(x, y);
    __nv_bfloat162 hb = *reinterpret_cast<__nv_bfloat162*>(&h);
    l = packbf(x - __bfloat162float(hb.x), y - __bfloat162float(hb.y));
}
__device__ __forceinline__ uint32_t packhf(float x, float y) {
    __half2 h = __floats2half2_rn(x, y);
    return *reinterpret_cast<uint32_t*>(&h);
}
__device__ __forceinline__ void splithf(float x, float y, uint32_t& h, uint32_t& l) {
    h = packhf(x, y);
    __half2 hh = *reinterpret_cast<__half2*>(&h);
    float2 hf = __half22float2(hh);
    l = packhf(x - hf.x, y - hf.y);
}
__device__ __forceinline__ uint32_t sptr(const void* p) {
    return (uint32_t)__cvta_generic_to_shared(p);
}
__device__ __forceinline__ void ldsm4(uint32_t addr, uint32_t& r0, uint32_t& r1,
                                      uint32_t& r2, uint32_t& r3) {
    asm volatile("ldmatrix.sync.aligned.m8n8.x4.shared.b16 {%0,%1,%2,%3}, [%4];"
                 : "=r"(r0), "=r"(r1), "=r"(r2), "=r"(r3) : "r"(addr));
}
__device__ __forceinline__ void ldsm4t(uint32_t addr, uint32_t& r0, uint32_t& r1,
                                       uint32_t& r2, uint32_t& r3) {
    asm volatile("ldmatrix.sync.aligned.m8n8.x4.trans.shared.b16 {%0,%1,%2,%3}, [%4];"
                 : "=r"(r0), "=r"(r1), "=r"(r2), "=r"(r3) : "r"(addr));
}
__device__ __forceinline__ void cpa16(uint32_t dst, const void* src) {
    asm volatile("cp.async.cg.shared.global [%0], [%1], 16;" :: "r"(dst), "l"(src));
}
#define CP_COMMIT() asm volatile("cp.async.commit_group;")
#define CP_WAIT0()  asm volatile("cp.async.wait_group 0;")

// ---------------------------------------------------------------------------
// Kernel 0: pre-convert x, w_qkv, w_proj to tf32 bit patterns
// ---------------------------------------------------------------------------
__global__ __launch_bounds__(256) void prep_kernel(
    const float* __restrict__ x, const float* __restrict__ wq,
    const float* __restrict__ wp)
{
    int i = blockIdx.x * 256 + threadIdx.x;
    const float4* src; float4* dst; int off;
    if (i < XTOT / 4)                { src = (const float4*)x;  dst = (float4*)g_X;  off = i; }
    else if (i < (XTOT + WQTOT) / 4) { src = (const float4*)wq; dst = (float4*)g_Wq; off = i - XTOT / 4; }
    else                             { src = (const float4*)wp; dst = (float4*)g_Wp; off = i - (XTOT + WQTOT) / 4; }
    float4 v = src[off];
    v.x = __uint_as_float(to_tf32(v.x));
    v.y = __uint_as_float(to_tf32(v.y));
    v.z = __uint_as_float(to_tf32(v.z));
    v.w = __uint_as_float(to_tf32(v.w));
    dst[off] = v;
}

// ---------------------------------------------------------------------------
// Kernel 1: QKV = gather(g_X, idx) @ g_Wq^T  (tf32 mma, 128x128 tile)
// Epilogue: Q fp32; K -> bf16 hi/lo; V -> fp16 hi/lo. All coalesced stores.
// ---------------------------------------------------------------------------
#define QPITCH 20
#define QSTGF (256 * QPITCH)
#define QSTGB (QSTGF * 4)

__global__ __launch_bounds__(256) void qkv_kernel(const int* __restrict__ idx)
{
    const int cBase = blockIdx.x * 128;
    const int rblk  = blockIdx.y;
    const int b     = rblk >> 5;
    const int jBase = (rblk & 31) * 128;

    __shared__ float sbuf[2][QSTGF];
    __shared__ int   sidx[128];

    const int tid = threadIdx.x;
    const int warp = tid >> 5, lane = tid & 31;
    const int g = lane >> 2, t = lane & 3;
    const int wm = warp >> 1, wn = warp & 1;
    const int mat = lane >> 3, r8 = lane & 7;

    if (tid < 128) sidx[tid] = idx[jBase + tid];
    __syncthreads();

    const float* aG = g_X + ((size_t)b * NN + sidx[tid >> 1]) * CC + (tid & 1) * 8;
    const float* bG = g_Wq + (size_t)(cBase + (tid >> 1)) * CC + (tid & 1) * 8;
    const uint32_t aDst = sptr(&sbuf[0][(tid >> 1) * QPITCH + (tid & 1) * 8]);
    const uint32_t bDst = sptr(&sbuf[0][128 * QPITCH + (tid >> 1) * QPITCH + (tid & 1) * 8]);

    const uint32_t aAddr0 = sptr(&sbuf[0][(wm * 32 + (mat & 1) * 8 + r8) * QPITCH + (mat >> 1) * 4]);
    const uint32_t bAddr0 = sptr(&sbuf[0][128 * QPITCH + (wn * 64 + (mat >> 1) * 8 + r8) * QPITCH + (mat & 1) * 4]);

#define QFILL(st, s) do {                                   \
        cpa16(aDst + (st) * QSTGB,      aG + (s) * 16);     \
        cpa16(aDst + (st) * QSTGB + 16, aG + (s) * 16 + 4); \
        cpa16(bDst + (st) * QSTGB,      bG + (s) * 16);     \
        cpa16(bDst + (st) * QSTGB + 16, bG + (s) * 16 + 4); \
        CP_COMMIT();                                         \
    } while (0)

    float acc[2][8][4] = {};

    QFILL(0, 0);

    for (int s = 0; s < 16; s++) {
        CP_WAIT0();
        __syncthreads();
        if (s < 15) QFILL((s + 1) & 1, s + 1);

        const uint32_t aA = aAddr0 + (s & 1) * QSTGB;
        const uint32_t bA = bAddr0 + (s & 1) * QSTGB;
#pragma unroll
        for (int ks = 0; ks < 2; ks++) {
            uint32_t af[2][4];
#pragma unroll
            for (int mt = 0; mt < 2; mt++)
                ldsm4(aA + (uint32_t)(mt * 16 * QPITCH + ks * 8) * 4,
                      af[mt][0], af[mt][1], af[mt][2], af[mt][3]);
#pragma unroll
            for (int p = 0; p < 4; p++) {
                uint32_t bf[4];
                ldsm4(bA + (uint32_t)(p * 16 * QPITCH + ks * 8) * 4,
                      bf[0], bf[1], bf[2], bf[3]);
                mma8(acc[0][p * 2],     af[0], bf[0], bf[1]);
                mma8(acc[1][p * 2],     af[1], bf[0], bf[1]);
                mma8(acc[0][p * 2 + 1], af[0], bf[2], bf[3]);
                mma8(acc[1][p * 2 + 1], af[1], bf[2], bf[3]);
            }
        }
    }

    // Epilogue
    const int cwb = cBase + wn * 64;
    const int s2 = cwb >> 8;
#pragma unroll
    for (int mt = 0; mt < 2; mt++) {
#pragma unroll
        for (int r = 0; r < 2; r++) {
            int j = jBase + wm * 32 + mt * 16 + g + r * 8;
            int gg = j >> 10, i = j & 1023;
#pragma unroll
            for (int nt = 0; nt < 8; nt++) {
                int c0 = cwb + nt * 8;
                int h = (c0 >> 5) & 7;
                int dd = (c0 & 31) + 2 * t;
                int bgh = (b * GG + gg) * HH + h;
                float v0 = acc[mt][nt][r * 2], v1 = acc[mt][nt][r * 2 + 1];
                size_t off = (size_t)bgh * NG * DD + (size_t)i * DD + dd;
                if (s2 == 0) {
                    *(float2*)&g_Q[off] = make_float2(v0, v1);
                } else if (s2 == 1) {
                    uint32_t hp, lp;
                    splitbf(v0, v1, hp, lp);
                    *(uint32_t*)&g_Khi[off] = hp;
                    *(uint32_t*)&g_Klo[off] = lp;
                } else {
                    uint32_t hp, lp;
                    splithf(v0, v1, hp, lp);
                    *(uint32_t*)&g_Vhi[off] = hp;
                    *(uint32_t*)&g_Vlo[off] = lp;
                }
            }
        }
    }
}

// ---------------------------------------------------------------------------
// Kernel 2: flash attention, static softmax. S: bf16 3-term. PV: fp16 P x
// fp16 V hi/lo (2 MMAs). 256 threads, grid (8, 128).
// ---------------------------------------------------------------------------
#define KP 40
#define KSTG (64 * KP * 2)

__global__ __launch_bounds__(256) void attn_kernel()
{
    const int bgh = blockIdx.y;

    __shared__ __nv_bfloat16 sKh[2][64][KP];
    __shared__ __nv_bfloat16 sKl[2][64][KP];
    __shared__ __half        sVh[2][64][KP];
    __shared__ __half        sVl[2][64][KP];

    const int tid = threadIdx.x;
    const int warp = tid >> 5, lane = tid & 31;
    const int g = lane >> 2, t = lane & 3;
    const int mat = lane >> 3, r8 = lane & 7;
    const int rbase = warp * 16;

    const size_t srcOff = (size_t)bgh * NG * DD + (tid >> 2) * 32 + (tid & 3) * 8;
    const __nv_bfloat16* kSrcH = g_Khi + srcOff;
    const __nv_bfloat16* kSrcL = g_Klo + srcOff;
    const __half*        vSrcH = g_Vhi + srcOff;
    const __half*        vSrcL = g_Vlo + srcOff;
    const uint32_t kDstH = sptr(&sKh[0][tid >> 2][(tid & 3) * 8]);
    const uint32_t kDstL = sptr(&sKl[0][tid >> 2][(tid & 3) * 8]);
    const uint32_t vDstH = sptr(&sVh[0][tid >> 2][(tid & 3) * 8]);
    const uint32_t vDstL = sptr(&sVl[0][tid >> 2][(tid & 3) * 8]);

#define ATTN_FILL(buf, kb) do {                                   \
        cpa16(kDstH + (buf) * KSTG, kSrcH + (size_t)(kb) * 2048); \
        cpa16(kDstL + (buf) * KSTG, kSrcL + (size_t)(kb) * 2048); \
        cpa16(vDstH + (buf) * KSTG, vSrcH + (size_t)(kb) * 2048); \
        cpa16(vDstL + (buf) * KSTG, vSrcL + (size_t)(kb) * 2048); \
    } while (0)

    ATTN_FILL(0, 0);
    CP_COMMIT();

    const uint32_t kAddrH = sptr(&sKh[0][(mat >> 1) * 8 + r8][(mat & 1) * 8]);
    const uint32_t kAddrL = sptr(&sKl[0][(mat >> 1) * 8 + r8][(mat & 1) * 8]);
    const uint32_t vAddrH = sptr(&sVh[0][(mat & 1) * 8 + r8][(mat >> 1) * 8]);
    const uint32_t vAddrL = sptr(&sVl[0][(mat & 1) * 8 + r8][(mat >> 1) * 8]);

    uint32_t qh[2][4], ql[2][4];
    {
        const float* Qw = g_Q + (size_t)bgh * NG * DD
                        + (size_t)(blockIdx.x * 128 + rbase) * DD;
#pragma unroll
        for (int s = 0; s < 2; s++) {
            float2 v0 = *(const float2*)&Qw[g * 32 + s * 16 + 2 * t];
            float2 v1 = *(const float2*)&Qw[(g + 8) * 32 + s * 16 + 2 * t];
            float2 v2 = *(const float2*)&Qw[g * 32 + s * 16 + 8 + 2 * t];
            float2 v3 = *(const float2*)&Qw[(g + 8) * 32 + s * 16 + 8 + 2 * t];
            splitbf(v0.x * QSCL, v0.y * QSCL, qh[s][0], ql[s][0]);
            splitbf(v1.x * QSCL, v1.y * QSCL, qh[s][1], ql[s][1]);
            splitbf(v2.x * QSCL, v2.y * QSCL, qh[s][2], ql[s][2]);
            splitbf(v3.x * QSCL, v3.y * QSCL, qh[s][3], ql[s][3]);
        }
    }

    float l0a = 0.f, l1a = 0.f;
    float oc[4][4] = {};

    for (int kb = 0; kb < 16; kb++) {
        const int cur = kb & 1;
        CP_WAIT0();
        __syncthreads();
        if (kb < 15) {
            ATTN_FILL(cur ^ 1, kb + 1);
            CP_COMMIT();
        }

        // --- S = Q K^T (3-term bf16) ---
        float sc[8][4];
#pragma unroll
        for (int nt = 0; nt < 8; nt++)
            sc[nt][0] = sc[nt][1] = sc[nt][2] = sc[nt][3] = 0.f;
#pragma unroll
        for (int s = 0; s < 2; s++) {
#pragma unroll
            for (int p = 0; p < 4; p++) {
                const uint32_t off = cur * KSTG + (uint32_t)(p * 16 * KP + s * 16) * 2;
                uint32_t kh[4], kl[4];
                ldsm4(kAddrH + off, kh[0], kh[1], kh[2], kh[3]);
                ldsm4(kAddrL + off, kl[0], kl[1], kl[2], kl[3]);
                mma16(sc[p * 2],     qh[s], kh[0], kh[1]);
                mma16(sc[p * 2],     qh[s], kl[0], kl[1]);
                mma16(sc[p * 2],     ql[s], kh[0], kh[1]);
                mma16(sc[p * 2 + 1], qh[s], kh[2], kh[3]);
                mma16(sc[p * 2 + 1], qh[s], kl[2], kl[3]);
                mma16(sc[p * 2 + 1], ql[s], kh[2], kh[3]);
            }
        }

        // --- static softmax: p = 2^sc, local l accumulation only ---
#pragma unroll
        for (int nt = 0; nt < 8; nt++) {
            sc[nt][0] = ex2(sc[nt][0]); l0a += sc[nt][0];
            sc[nt][1] = ex2(sc[nt][1]); l0a += sc[nt][1];
            sc[nt][2] = ex2(sc[nt][2]); l1a += sc[nt][2];
            sc[nt][3] = ex2(sc[nt][3]); l1a += sc[nt][3];
        }

        // --- O += P @ V (fp16 P single-term x fp16 V hi/lo: 2 MMAs) ---
#pragma unroll
        for (int s = 0; s < 4; s++) {
            uint32_t ap[4];
            ap[0] = packhf(sc[2 * s][0],     sc[2 * s][1]);
            ap[1] = packhf(sc[2 * s][2],     sc[2 * s][3]);
            ap[2] = packhf(sc[2 * s + 1][0], sc[2 * s + 1][1]);
            ap[3] = packhf(sc[2 * s + 1][2], sc[2 * s + 1][3]);
            const uint32_t off = cur * KSTG + (uint32_t)(s * 16 * KP) * 2;
            uint32_t vh[4], vl[4];
            ldsm4t(vAddrH + off, vh[0], vh[1], vh[2], vh[3]);
            ldsm4t(vAddrL + off, vl[0], vl[1], vl[2], vl[3]);
            mma16h(oc[0], ap, vh[0], vh[1]);
            mma16h(oc[0], ap, vl[0], vl[1]);
            mma16h(oc[1], ap, vh[2], vh[3]);
            mma16h(oc[1], ap, vl[2], vl[3]);
            const uint32_t off2 = off + 16 * 2;
            ldsm4t(vAddrH + off2, vh[0], vh[1], vh[2], vh[3]);
            ldsm4t(vAddrL + off2, vl[0], vl[1], vl[2], vl[3]);
            mma16h(oc[2], ap, vh[0], vh[1]);
            mma16h(oc[2], ap, vl[0], vl[1]);
            mma16h(oc[3], ap, vh[2], vh[3]);
            mma16h(oc[3], ap, vl[2], vl[3]);
        }
    }

    l0a += __shfl_xor_sync(0xffffffffu, l0a, 1);
    l0a += __shfl_xor_sync(0xffffffffu, l0a, 2);
    l1a += __shfl_xor_sync(0xffffffffu, l1a, 1);
    l1a += __shfl_xor_sync(0xffffffffu, l1a, 2);

    const int b = bgh >> 5, gg = (bgh >> 3) & 3, h = bgh & 7;
    float inv0 = 1.f / l0a, inv1 = 1.f / l1a;
    int i0 = blockIdx.x * 128 + rbase + g;
    size_t row0 = ((size_t)b * NN + (size_t)gg * NG + i0) * CC + h * DD;
    size_t row1 = row0 + (size_t)8 * CC;
#pragma unroll
    for (int nt = 0; nt < 4; nt++) {
        *(float2*)&g_O[row0 + nt * 8 + 2 * t] =
            make_float2(__uint_as_float(to_tf32(oc[nt][0] * inv0)),
                        __uint_as_float(to_tf32(oc[nt][1] * inv0)));
        *(float2*)&g_O[row1 + nt * 8 + 2 * t] =
            make_float2(__uint_as_float(to_tf32(oc[nt][2] * inv1)),
                        __uint_as_float(to_tf32(oc[nt][3] * inv1)));
    }
}

// ---------------------------------------------------------------------------
// Kernel 3: out[b, idx[j], :] = g_O[b, j, :] @ g_Wp^T + bias
// 128x128 tile, grid (2, 128), 256 thr.
// ---------------------------------------------------------------------------
__global__ __launch_bounds__(256) void proj_kernel(
    const int* __restrict__ idx, const float* __restrict__ bias,
    float* __restrict__ out)
{
    const int cBase = blockIdx.x * 128;
    const int rblk  = blockIdx.y;
    const int b     = rblk >> 5;
    const int jBase = (rblk & 31) * 128;

    __shared__ float sbuf[2][QSTGF];
    __shared__ int   sidx[128];

    const int tid = threadIdx.x;
    const int warp = tid >> 5, lane = tid & 31;
    const int g = lane >> 2, t = lane & 3;
    const int wm = warp >> 1, wn = warp & 1;
    const int mat = lane >> 3, r8 = lane & 7;

    if (tid < 128) sidx[tid] = idx[jBase + tid];
    __syncthreads();

    const float* aG = g_O + ((size_t)b * NN + jBase + (tid >> 1)) * CC + (tid & 1) * 8;
    const float* bG = g_Wp + (size_t)(cBase + (tid >> 1)) * CC + (tid & 1) * 8;
    const uint32_t aDst = sptr(&sbuf[0][(tid >> 1) * QPITCH + (tid & 1) * 8]);
    const uint32_t bDst = sptr(&sbuf[0][128 * QPITCH + (tid >> 1) * QPITCH + (tid & 1) * 8]);

    const uint32_t aAddr0 = sptr(&sbuf[0][(wm * 32 + (mat & 1) * 8 + r8) * QPITCH + (mat >> 1) * 4]);
    const uint32_t bAddr0 = sptr(&sbuf[0][128 * QPITCH + (wn * 64 + (mat >> 1) * 8 + r8) * QPITCH + (mat & 1) * 4]);

    float acc[2][8][4] = {};

    QFILL(0, 0);

    for (int s = 0; s < 16; s++) {
        CP_WAIT0();
        __syncthreads();
        if (s < 15) QFILL((s + 1) & 1, s + 1);

        const uint32_t aA = aAddr0 + (s & 1) * QSTGB;
        const uint32_t bA = bAddr0 + (s & 1) * QSTGB;
#pragma unroll
        for (int ks = 0; ks < 2; ks++) {
            uint32_t af[2][4];
#pragma unroll
            for (int mt = 0; mt < 2; mt++)
                ldsm4(aA + (uint32_t)(mt * 16 * QPITCH + ks * 8) * 4,
                      af[mt][0], af[mt][1], af[mt][2], af[mt][3]);
#pragma unroll
            for (int p = 0; p < 4; p++) {
                uint32_t bf[4];
                ldsm4(bA + (uint32_t)(p * 16 * QPITCH + ks * 8) * 4,
                      bf[0], bf[1], bf[2], bf[3]);
                mma8(acc[0][p * 2],     af[0], bf[0], bf[1]);
                mma8(acc[1][p * 2],     af[1], bf[0], bf[1]);
                mma8(acc[0][p * 2 + 1], af[0], bf[2], bf[3]);
                mma8(acc[1][p * 2 + 1], af[1], bf[2], bf[3]);
            }
        }
    }

    // Epilogue: bias + inverse-permutation row scatter
    const int cwb = cBase + wn * 64;
    float2 bb[8];
#pragma unroll
    for (int nt = 0; nt < 8; nt++)
        bb[nt] = *(const float2*)&bias[cwb + nt * 8 + 2 * t];

#pragma unroll
    for (int mt = 0; mt < 2; mt++) {
#pragma unroll
        for (int r = 0; r < 2; r++) {
            int jl = wm * 32 + mt * 16 + g + r * 8;
            int orow = sidx[jl];
            size_t base = ((size_t)b * NN + orow) * CC + cwb;
#pragma unroll
            for (int nt = 0; nt < 8; nt++) {
                *(float2*)&out[base + nt * 8 + 2 * t] =
                    make_float2(acc[mt][nt][r * 2] + bb[nt].x,
                                acc[mt][nt][r * 2 + 1] + bb[nt].y);
            }
        }
    }
}

// ---------------------------------------------------------------------------
extern "C" void kernel_launch(void* const* d_in, const int* in_sizes, int n_in,
                              void* d_out, int out_size)
{
    (void)in_sizes; (void)n_in; (void)out_size;
    const float* x      = (const float*)d_in[0];
    const int*   idx    = (const int*)d_in[1];
    const float* w_qkv  = (const float*)d_in[2];
    const float* w_proj = (const float*)d_in[3];
    const float* b_proj = (const float*)d_in[4];
    float* out = (float*)d_out;

    prep_kernel<<<(XTOT + WQTOT + WPTOT) / 4 / 256, 256>>>(x, w_qkv, w_proj);
    qkv_kernel<<<dim3(6, 128), 256>>>(idx);
    attn_kernel<<<dim3(8, 128), 256>>>();
    proj_kernel<<<dim3(2, 128), 256>>>(idx, b_proj, out);
}

// round 15
// speedup vs baseline: 1.2837x; 1.0603x over previous
#include <cuda_runtime.h>
#include <cuda_bf16.h>
#include <cuda_fp16.h>
#include <math.h>
#include <stdint.h>

// Problem constants
#define BB 4
#define NN 4096
#define CC 256
#define HH 8
#define GG 4
#define DD 32
#define NG 1024
#define QSCL (0.17677669529663687f * 1.4426950408889634f)  // 1/sqrt(32)*log2(e)

#define XTOT  (BB * NN * CC)
#define WQTOT (3 * CC * CC)
#define WPTOT (CC * CC)

// Scratch (device globals; allocation-free)
__device__ float g_X[XTOT];
__device__ float g_Wq[WQTOT];
__device__ float g_Wp[WPTOT];
__device__ float g_Q[BB * GG * HH * NG * DD];
__device__ __half g_Khi[BB * GG * HH * NG * DD];          // [bgh][i][d] fp16
__device__ __half g_Klo[BB * GG * HH * NG * DD];
__device__ __half g_Vhi[BB * GG * HH * NG * DD];          // [bgh][i][d] fp16
__device__ __half g_Vlo[BB * GG * HH * NG * DD];
__device__ float g_O[BB * NN * CC];                        // tf32 bits

// ---------------------------------------------------------------------------
// PTX helpers
// ---------------------------------------------------------------------------
__device__ __forceinline__ void mma8(float c[4], const uint32_t a[4],
                                     uint32_t b0, uint32_t b1) {
    asm volatile(
        "mma.sync.aligned.m16n8k8.row.col.f32.tf32.tf32.f32 "
        "{%0,%1,%2,%3}, {%4,%5,%6,%7}, {%8,%9}, {%0,%1,%2,%3};"
        : "+f"(c[0]), "+f"(c[1]), "+f"(c[2]), "+f"(c[3])
        : "r"(a[0]), "r"(a[1]), "r"(a[2]), "r"(a[3]), "r"(b0), "r"(b1));
}
__device__ __forceinline__ void mma16h(float c[4], const uint32_t a[4],
                                       uint32_t b0, uint32_t b1) {
    asm volatile(
        "mma.sync.aligned.m16n8k16.row.col.f32.f16.f16.f32 "
        "{%0,%1,%2,%3}, {%4,%5,%6,%7}, {%8,%9}, {%0,%1,%2,%3};"
        : "+f"(c[0]), "+f"(c[1]), "+f"(c[2]), "+f"(c[3])
        : "r"(a[0]), "r"(a[1]), "r"(a[2]), "r"(a[3]), "r"(b0), "r"(b1));
}
__device__ __forceinline__ uint32_t to_tf32(float x) {
    uint32_t h; asm("cvt.rna.tf32.f32 %0, %1;" : "=r"(h) : "f"(x)); return h;
}
__device__ __forceinline__ float ex2(float x) {
    float r; asm("ex2.approx.ftz.f32 %0, %1;" : "=f"(r) : "f"(x)); return r;
}
__device__ __forceinline__ uint32_t packhf(float x, float y) {
    __half2 h = __floats2half2_rn(x, y);
    return *reinterpret_cast<uint32_t*>(&h);
}
__device__ __forceinline__ void splithf(float x, float y, uint32_t& h, uint32_t& l) {
    h = packhf(x, y);
    __half2 hh = *reinterpret_cast<__half2*>(&h);
    float2 hf = __half22float2(hh);
    l = packhf(x - hf.x, y - hf.y);
}
__device__ __forceinline__ uint32_t sptr(const void* p) {
    return (uint32_t)__cvta_generic_to_shared(p);
}
__device__ __forceinline__ void ldsm4(uint32_t addr, uint32_t& r0, uint32_t& r1,
                                      uint32_t& r2, uint32_t& r3) {
    asm volatile("ldmatrix.sync.aligned.m8n8.x4.shared.b16 {%0,%1,%2,%3}, [%4];"
                 : "=r"(r0), "=r"(r1), "=r"(r2), "=r"(r3) : "r"(addr));
}
__device__ __forceinline__ void ldsm4t(uint32_t addr, uint32_t& r0, uint32_t& r1,
                                       uint32_t& r2, uint32_t& r3) {
    asm volatile("ldmatrix.sync.aligned.m8n8.x4.trans.shared.b16 {%0,%1,%2,%3}, [%4];"
                 : "=r"(r0), "=r"(r1), "=r"(r2), "=r"(r3) : "r"(addr));
}
__device__ __forceinline__ void cpa16(uint32_t dst, const void* src) {
    asm volatile("cp.async.cg.shared.global [%0], [%1], 16;" :: "r"(dst), "l"(src));
}
#define CP_COMMIT() asm volatile("cp.async.commit_group;")
#define CP_WAIT0()  asm volatile("cp.async.wait_group 0;")

// ---------------------------------------------------------------------------
// Kernel 0: pre-convert x, w_qkv, w_proj to tf32 bit patterns
// ---------------------------------------------------------------------------
__global__ __launch_bounds__(256) void prep_kernel(
    const float* __restrict__ x, const float* __restrict__ wq,
    const float* __restrict__ wp)
{
    int i = blockIdx.x * 256 + threadIdx.x;
    const float4* src; float4* dst; int off;
    if (i < XTOT / 4)                { src = (const float4*)x;  dst = (float4*)g_X;  off = i; }
    else if (i < (XTOT + WQTOT) / 4) { src = (const float4*)wq; dst = (float4*)g_Wq; off = i - XTOT / 4; }
    else                             { src = (const float4*)wp; dst = (float4*)g_Wp; off = i - (XTOT + WQTOT) / 4; }
    float4 v = src[off];
    v.x = __uint_as_float(to_tf32(v.x));
    v.y = __uint_as_float(to_tf32(v.y));
    v.z = __uint_as_float(to_tf32(v.z));
    v.w = __uint_as_float(to_tf32(v.w));
    dst[off] = v;
}

// ---------------------------------------------------------------------------
// Kernel 1: QKV = gather(g_X, idx) @ g_Wq^T  (tf32 mma, 128x128 tile)
// Epilogue: Q fp32; K and V -> fp16 hi/lo. All coalesced stores.
// ---------------------------------------------------------------------------
#define QPITCH 20
#define QSTGF (256 * QPITCH)
#define QSTGB (QSTGF * 4)

__global__ __launch_bounds__(256) void qkv_kernel(const int* __restrict__ idx)
{
    const int cBase = blockIdx.x * 128;
    const int rblk  = blockIdx.y;
    const int b     = rblk >> 5;
    const int jBase = (rblk & 31) * 128;

    __shared__ float sbuf[2][QSTGF];
    __shared__ int   sidx[128];

    const int tid = threadIdx.x;
    const int warp = tid >> 5, lane = tid & 31;
    const int g = lane >> 2, t = lane & 3;
    const int wm = warp >> 1, wn = warp & 1;
    const int mat = lane >> 3, r8 = lane & 7;

    if (tid < 128) sidx[tid] = idx[jBase + tid];
    __syncthreads();

    const float* aG = g_X + ((size_t)b * NN + sidx[tid >> 1]) * CC + (tid & 1) * 8;
    const float* bG = g_Wq + (size_t)(cBase + (tid >> 1)) * CC + (tid & 1) * 8;
    const uint32_t aDst = sptr(&sbuf[0][(tid >> 1) * QPITCH + (tid & 1) * 8]);
    const uint32_t bDst = sptr(&sbuf[0][128 * QPITCH + (tid >> 1) * QPITCH + (tid & 1) * 8]);

    const uint32_t aAddr0 = sptr(&sbuf[0][(wm * 32 + (mat & 1) * 8 + r8) * QPITCH + (mat >> 1) * 4]);
    const uint32_t bAddr0 = sptr(&sbuf[0][128 * QPITCH + (wn * 64 + (mat >> 1) * 8 + r8) * QPITCH + (mat & 1) * 4]);

#define QFILL(st, s) do {                                   \
        cpa16(aDst + (st) * QSTGB,      aG + (s) * 16);     \
        cpa16(aDst + (st) * QSTGB + 16, aG + (s) * 16 + 4); \
        cpa16(bDst + (st) * QSTGB,      bG + (s) * 16);     \
        cpa16(bDst + (st) * QSTGB + 16, bG + (s) * 16 + 4); \
        CP_COMMIT();                                         \
    } while (0)

    float acc[2][8][4] = {};

    QFILL(0, 0);

    for (int s = 0; s < 16; s++) {
        CP_WAIT0();
        __syncthreads();
        if (s < 15) QFILL((s + 1) & 1, s + 1);

        const uint32_t aA = aAddr0 + (s & 1) * QSTGB;
        const uint32_t bA = bAddr0 + (s & 1) * QSTGB;
#pragma unroll
        for (int ks = 0; ks < 2; ks++) {
            uint32_t af[2][4];
#pragma unroll
            for (int mt = 0; mt < 2; mt++)
                ldsm4(aA + (uint32_t)(mt * 16 * QPITCH + ks * 8) * 4,
                      af[mt][0], af[mt][1], af[mt][2], af[mt][3]);
#pragma unroll
            for (int p = 0; p < 4; p++) {
                uint32_t bf[4];
                ldsm4(bA + (uint32_t)(p * 16 * QPITCH + ks * 8) * 4,
                      bf[0], bf[1], bf[2], bf[3]);
                mma8(acc[0][p * 2],     af[0], bf[0], bf[1]);
                mma8(acc[1][p * 2],     af[1], bf[0], bf[1]);
                mma8(acc[0][p * 2 + 1], af[0], bf[2], bf[3]);
                mma8(acc[1][p * 2 + 1], af[1], bf[2], bf[3]);
            }
        }
    }

    // Epilogue
    const int cwb = cBase + wn * 64;
    const int s2 = cwb >> 8;
#pragma unroll
    for (int mt = 0; mt < 2; mt++) {
#pragma unroll
        for (int r = 0; r < 2; r++) {
            int j = jBase + wm * 32 + mt * 16 + g + r * 8;
            int gg = j >> 10, i = j & 1023;
#pragma unroll
            for (int nt = 0; nt < 8; nt++) {
                int c0 = cwb + nt * 8;
                int h = (c0 >> 5) & 7;
                int dd = (c0 & 31) + 2 * t;
                int bgh = (b * GG + gg) * HH + h;
                float v0 = acc[mt][nt][r * 2], v1 = acc[mt][nt][r * 2 + 1];
                size_t off = (size_t)bgh * NG * DD + (size_t)i * DD + dd;
                if (s2 == 0) {
                    *(float2*)&g_Q[off] = make_float2(v0, v1);
                } else {
                    uint32_t hp, lp;
                    splithf(v0, v1, hp, lp);
                    __half* dh = (s2 == 1) ? g_Khi : g_Vhi;
                    __half* dl = (s2 == 1) ? g_Klo : g_Vlo;
                    *(uint32_t*)&dh[off] = hp;
                    *(uint32_t*)&dl[off] = lp;
                }
            }
        }
    }
}

// ---------------------------------------------------------------------------
// Kernel 2: flash attention, static softmax.
// S: fp16 2-term (qh x (kh + kl)). PV: fp16 P x fp16 V hi/lo (2 MMAs).
// 256 threads, grid (8, 128).
// ---------------------------------------------------------------------------
#define KP 40
#define KSTG (64 * KP * 2)

__global__ __launch_bounds__(256) void attn_kernel()
{
    const int bgh = blockIdx.y;

    __shared__ __half sKh[2][64][KP];
    __shared__ __half sKl[2][64][KP];
    __shared__ __half sVh[2][64][KP];
    __shared__ __half sVl[2][64][KP];

    const int tid = threadIdx.x;
    const int warp = tid >> 5, lane = tid & 31;
    const int g = lane >> 2, t = lane & 3;
    const int mat = lane >> 3, r8 = lane & 7;
    const int rbase = warp * 16;

    const size_t srcOff = (size_t)bgh * NG * DD + (tid >> 2) * 32 + (tid & 3) * 8;
    const __half* kSrcH = g_Khi + srcOff;
    const __half* kSrcL = g_Klo + srcOff;
    const __half* vSrcH = g_Vhi + srcOff;
    const __half* vSrcL = g_Vlo + srcOff;
    const uint32_t kDstH = sptr(&sKh[0][tid >> 2][(tid & 3) * 8]);
    const uint32_t kDstL = sptr(&sKl[0][tid >> 2][(tid & 3) * 8]);
    const uint32_t vDstH = sptr(&sVh[0][tid >> 2][(tid & 3) * 8]);
    const uint32_t vDstL = sptr(&sVl[0][tid >> 2][(tid & 3) * 8]);

#define ATTN_FILL(buf, kb) do {                                   \
        cpa16(kDstH + (buf) * KSTG, kSrcH + (size_t)(kb) * 2048); \
        cpa16(kDstL + (buf) * KSTG, kSrcL + (size_t)(kb) * 2048); \
        cpa16(vDstH + (buf) * KSTG, vSrcH + (size_t)(kb) * 2048); \
        cpa16(vDstL + (buf) * KSTG, vSrcL + (size_t)(kb) * 2048); \
    } while (0)

    ATTN_FILL(0, 0);
    CP_COMMIT();

    const uint32_t kAddrH = sptr(&sKh[0][(mat >> 1) * 8 + r8][(mat & 1) * 8]);
    const uint32_t kAddrL = sptr(&sKl[0][(mat >> 1) * 8 + r8][(mat & 1) * 8]);
    const uint32_t vAddrH = sptr(&sVh[0][(mat & 1) * 8 + r8][(mat >> 1) * 8]);
    const uint32_t vAddrL = sptr(&sVl[0][(mat & 1) * 8 + r8][(mat >> 1) * 8]);

    // Q fragments (pre-scaled by SCALE*log2e, fp16 hi only), in registers
    uint32_t qh[2][4];
    {
        const float* Qw = g_Q + (size_t)bgh * NG * DD
                        + (size_t)(blockIdx.x * 128 + rbase) * DD;
#pragma unroll
        for (int s = 0; s < 2; s++) {
            float2 v0 = *(const float2*)&Qw[g * 32 + s * 16 + 2 * t];
            float2 v1 = *(const float2*)&Qw[(g + 8) * 32 + s * 16 + 2 * t];
            float2 v2 = *(const float2*)&Qw[g * 32 + s * 16 + 8 + 2 * t];
            float2 v3 = *(const float2*)&Qw[(g + 8) * 32 + s * 16 + 8 + 2 * t];
            qh[s][0] = packhf(v0.x * QSCL, v0.y * QSCL);
            qh[s][1] = packhf(v1.x * QSCL, v1.y * QSCL);
            qh[s][2] = packhf(v2.x * QSCL, v2.y * QSCL);
            qh[s][3] = packhf(v3.x * QSCL, v3.y * QSCL);
        }
    }

    float l0a = 0.f, l1a = 0.f;
    float oc[4][4] = {};

    for (int kb = 0; kb < 16; kb++) {
        const int cur = kb & 1;
        CP_WAIT0();
        __syncthreads();
        if (kb < 15) {
            ATTN_FILL(cur ^ 1, kb + 1);
            CP_COMMIT();
        }

        // --- S = Q K^T (fp16 2-term: qh x kh + qh x kl) ---
        float sc[8][4];
#pragma unroll
        for (int nt = 0; nt < 8; nt++)
            sc[nt][0] = sc[nt][1] = sc[nt][2] = sc[nt][3] = 0.f;
#pragma unroll
        for (int s = 0; s < 2; s++) {
#pragma unroll
            for (int p = 0; p < 4; p++) {
                const uint32_t off = cur * KSTG + (uint32_t)(p * 16 * KP + s * 16) * 2;
                uint32_t kh[4], kl[4];
                ldsm4(kAddrH + off, kh[0], kh[1], kh[2], kh[3]);
                ldsm4(kAddrL + off, kl[0], kl[1], kl[2], kl[3]);
                mma16h(sc[p * 2],     qh[s], kh[0], kh[1]);
                mma16h(sc[p * 2],     qh[s], kl[0], kl[1]);
                mma16h(sc[p * 2 + 1], qh[s], kh[2], kh[3]);
                mma16h(sc[p * 2 + 1], qh[s], kl[2], kl[3]);
            }
        }

        // --- static softmax: p = 2^sc, local l accumulation only ---
#pragma unroll
        for (int nt = 0; nt < 8; nt++) {
            sc[nt][0] = ex2(sc[nt][0]); l0a += sc[nt][0];
            sc[nt][1] = ex2(sc[nt][1]); l0a += sc[nt][1];
            sc[nt][2] = ex2(sc[nt][2]); l1a += sc[nt][2];
            sc[nt][3] = ex2(sc[nt][3]); l1a += sc[nt][3];
        }

        // --- O += P @ V (fp16 P single-term x fp16 V hi/lo: 2 MMAs) ---
#pragma unroll
        for (int s = 0; s < 4; s++) {
            uint32_t ap[4];
            ap[0] = packhf(sc[2 * s][0],     sc[2 * s][1]);
            ap[1] = packhf(sc[2 * s][2],     sc[2 * s][3]);
            ap[2] = packhf(sc[2 * s + 1][0], sc[2 * s + 1][1]);
            ap[3] = packhf(sc[2 * s + 1][2], sc[2 * s + 1][3]);
            const uint32_t off = cur * KSTG + (uint32_t)(s * 16 * KP) * 2;
            uint32_t vh[4], vl[4];
            ldsm4t(vAddrH + off, vh[0], vh[1], vh[2], vh[3]);
            ldsm4t(vAddrL + off, vl[0], vl[1], vl[2], vl[3]);
            mma16h(oc[0], ap, vh[0], vh[1]);
            mma16h(oc[0], ap, vl[0], vl[1]);
            mma16h(oc[1], ap, vh[2], vh[3]);
            mma16h(oc[1], ap, vl[2], vl[3]);
            const uint32_t off2 = off + 16 * 2;
            ldsm4t(vAddrH + off2, vh[0], vh[1], vh[2], vh[3]);
            ldsm4t(vAddrL + off2, vl[0], vl[1], vl[2], vl[3]);
            mma16h(oc[2], ap, vh[0], vh[1]);
            mma16h(oc[2], ap, vl[0], vl[1]);
            mma16h(oc[3], ap, vh[2], vh[3]);
            mma16h(oc[3], ap, vl[2], vl[3]);
        }
    }

    l0a += __shfl_xor_sync(0xffffffffu, l0a, 1);
    l0a += __shfl_xor_sync(0xffffffffu, l0a, 2);
    l1a += __shfl_xor_sync(0xffffffffu, l1a, 1);
    l1a += __shfl_xor_sync(0xffffffffu, l1a, 2);

    const int b = bgh >> 5, gg = (bgh >> 3) & 3, h = bgh & 7;
    float inv0 = 1.f / l0a, inv1 = 1.f / l1a;
    int i0 = blockIdx.x * 128 + rbase + g;
    size_t row0 = ((size_t)b * NN + (size_t)gg * NG + i0) * CC + h * DD;
    size_t row1 = row0 + (size_t)8 * CC;
#pragma unroll
    for (int nt = 0; nt < 4; nt++) {
        *(float2*)&g_O[row0 + nt * 8 + 2 * t] =
            make_float2(__uint_as_float(to_tf32(oc[nt][0] * inv0)),
                        __uint_as_float(to_tf32(oc[nt][1] * inv0)));
        *(float2*)&g_O[row1 + nt * 8 + 2 * t] =
            make_float2(__uint_as_float(to_tf32(oc[nt][2] * inv1)),
                        __uint_as_float(to_tf32(oc[nt][3] * inv1)));
    }
}

// ---------------------------------------------------------------------------
// Kernel 3: out[b, idx[j], :] = g_O[b, j, :] @ g_Wp^T + bias
// 128x128 tile, grid (2, 128), 256 thr.
// ---------------------------------------------------------------------------
__global__ __launch_bounds__(256) void proj_kernel(
    const int* __restrict__ idx, const float* __restrict__ bias,
    float* __restrict__ out)
{
    const int cBase = blockIdx.x * 128;
    const int rblk  = blockIdx.y;
    const int b     = rblk >> 5;
    const int jBase = (rblk & 31) * 128;

    __shared__ float sbuf[2][QSTGF];
    __shared__ int   sidx[128];

    const int tid = threadIdx.x;
    const int warp = tid >> 5, lane = tid & 31;
    const int g = lane >> 2, t = lane & 3;
    const int wm = warp >> 1, wn = warp & 1;
    const int mat = lane >> 3, r8 = lane & 7;

    if (tid < 128) sidx[tid] = idx[jBase + tid];
    __syncthreads();

    const float* aG = g_O + ((size_t)b * NN + jBase + (tid >> 1)) * CC + (tid & 1) * 8;
    const float* bG = g_Wp + (size_t)(cBase + (tid >> 1)) * CC + (tid & 1) * 8;
    const uint32_t aDst = sptr(&sbuf[0][(tid >> 1) * QPITCH + (tid & 1) * 8]);
    const uint32_t bDst = sptr(&sbuf[0][128 * QPITCH + (tid >> 1) * QPITCH + (tid & 1) * 8]);

    const uint32_t aAddr0 = sptr(&sbuf[0][(wm * 32 + (mat & 1) * 8 + r8) * QPITCH + (mat >> 1) * 4]);
    const uint32_t bAddr0 = sptr(&sbuf[0][128 * QPITCH + (wn * 64 + (mat >> 1) * 8 + r8) * QPITCH + (mat & 1) * 4]);

    float acc[2][8][4] = {};

    QFILL(0, 0);

    for (int s = 0; s < 16; s++) {
        CP_WAIT0();
        __syncthreads();
        if (s < 15) QFILL((s + 1) & 1, s + 1);

        const uint32_t aA = aAddr0 + (s & 1) * QSTGB;
        const uint32_t bA = bAddr0 + (s & 1) * QSTGB;
#pragma unroll
        for (int ks = 0; ks < 2; ks++) {
            uint32_t af[2][4];
#pragma unroll
            for (int mt = 0; mt < 2; mt++)
                ldsm4(aA + (uint32_t)(mt * 16 * QPITCH + ks * 8) * 4,
                      af[mt][0], af[mt][1], af[mt][2], af[mt][3]);
#pragma unroll
            for (int p = 0; p < 4; p++) {
                uint32_t bf[4];
                ldsm4(bA + (uint32_t)(p * 16 * QPITCH + ks * 8) * 4,
                      bf[0], bf[1], bf[2], bf[3]);
                mma8(acc[0][p * 2],     af[0], bf[0], bf[1]);
                mma8(acc[1][p * 2],     af[1], bf[0], bf[1]);
                mma8(acc[0][p * 2 + 1], af[0], bf[2], bf[3]);
                mma8(acc[1][p * 2 + 1], af[1], bf[2], bf[3]);
            }
        }
    }

    // Epilogue: bias + inverse-permutation row scatter
    const int cwb = cBase + wn * 64;
    float2 bb[8];
#pragma unroll
    for (int nt = 0; nt < 8; nt++)
        bb[nt] = *(const float2*)&bias[cwb + nt * 8 + 2 * t];

#pragma unroll
    for (int mt = 0; mt < 2; mt++) {
#pragma unroll
        for (int r = 0; r < 2; r++) {
            int jl = wm * 32 + mt * 16 + g + r * 8;
            int orow = sidx[jl];
            size_t base = ((size_t)b * NN + orow) * CC + cwb;
#pragma unroll
            for (int nt = 0; nt < 8; nt++) {
                *(float2*)&out[base + nt * 8 + 2 * t] =
                    make_float2(acc[mt][nt][r * 2] + bb[nt].x,
                                acc[mt][nt][r * 2 + 1] + bb[nt].y);
            }
        }
    }
}

// ---------------------------------------------------------------------------
extern "C" void kernel_launch(void* const* d_in, const int* in_sizes, int n_in,
                              void* d_out, int out_size)
{
    (void)in_sizes; (void)n_in; (void)out_size;
    const float* x      = (const float*)d_in[0];
    const int*   idx    = (const int*)d_in[1];
    const float* w_qkv  = (const float*)d_in[2];
    const float* w_proj = (const float*)d_in[3];
    const float* b_proj = (const float*)d_in[4];
    float* out = (float*)d_out;

    prep_kernel<<<(XTOT + WQTOT + WPTOT) / 4 / 256, 256>>>(x, w_qkv, w_proj);
    qkv_kernel<<<dim3(6, 128), 256>>>(idx);
    attn_kernel<<<dim3(8, 128), 256>>>();
    proj_kernel<<<dim3(2, 128), 256>>>(idx, b_proj, out);
}

// round 16
// speedup vs baseline: 1.5790x; 1.2301x over previous
#include <cuda_runtime.h>
#include <cuda_fp16.h>
#include <math.h>
#include <stdint.h>

// Problem constants
#define BB 4
#define NN 4096
#define CC 256
#define HH 8
#define GG 4
#define DD 32
#define NG 1024
#define QSCL (0.17677669529663687f * 1.4426950408889634f)  // 1/sqrt(32)*log2(e)

#define XTOT  (BB * NN * CC)
#define WQTOT (3 * CC * CC)
#define WPTOT (CC * CC)

// Scratch (device globals; allocation-free)
__device__ __half g_Xh[XTOT];
__device__ __half g_Wqh[WQTOT];
__device__ __half g_Wph[WPTOT];
__device__ __half g_Qh[BB * GG * HH * NG * DD];           // pre-scaled by QSCL
__device__ __half g_Khi[BB * GG * HH * NG * DD];          // [bgh][i][d]
__device__ __half g_Klo[BB * GG * HH * NG * DD];
__device__ __half g_Vhi[BB * GG * HH * NG * DD];
__device__ __half g_Vlo[BB * GG * HH * NG * DD];
__device__ __half g_Oh[BB * NN * CC];                     // attention out fp16

// ---------------------------------------------------------------------------
// PTX helpers
// ---------------------------------------------------------------------------
__device__ __forceinline__ void mma16h(float c[4], const uint32_t a[4],
                                       uint32_t b0, uint32_t b1) {
    asm volatile(
        "mma.sync.aligned.m16n8k16.row.col.f32.f16.f16.f32 "
        "{%0,%1,%2,%3}, {%4,%5,%6,%7}, {%8,%9}, {%0,%1,%2,%3};"
        : "+f"(c[0]), "+f"(c[1]), "+f"(c[2]), "+f"(c[3])
        : "r"(a[0]), "r"(a[1]), "r"(a[2]), "r"(a[3]), "r"(b0), "r"(b1));
}
__device__ __forceinline__ float ex2(float x) {
    float r; asm("ex2.approx.ftz.f32 %0, %1;" : "=f"(r) : "f"(x)); return r;
}
__device__ __forceinline__ uint32_t packhf(float x, float y) {
    __half2 h = __floats2half2_rn(x, y);
    return *reinterpret_cast<uint32_t*>(&h);
}
__device__ __forceinline__ void splithf(float x, float y, uint32_t& h, uint32_t& l) {
    h = packhf(x, y);
    __half2 hh = *reinterpret_cast<__half2*>(&h);
    float2 hf = __half22float2(hh);
    l = packhf(x - hf.x, y - hf.y);
}
__device__ __forceinline__ uint32_t sptr(const void* p) {
    return (uint32_t)__cvta_generic_to_shared(p);
}
__device__ __forceinline__ void ldsm4(uint32_t addr, uint32_t& r0, uint32_t& r1,
                                      uint32_t& r2, uint32_t& r3) {
    asm volatile("ldmatrix.sync.aligned.m8n8.x4.shared.b16 {%0,%1,%2,%3}, [%4];"
                 : "=r"(r0), "=r"(r1), "=r"(r2), "=r"(r3) : "r"(addr));
}
__device__ __forceinline__ void ldsm4t(uint32_t addr, uint32_t& r0, uint32_t& r1,
                                       uint32_t& r2, uint32_t& r3) {
    asm volatile("ldmatrix.sync.aligned.m8n8.x4.trans.shared.b16 {%0,%1,%2,%3}, [%4];"
                 : "=r"(r0), "=r"(r1), "=r"(r2), "=r"(r3) : "r"(addr));
}
__device__ __forceinline__ void cpa16(uint32_t dst, const void* src) {
    asm volatile("cp.async.cg.shared.global [%0], [%1], 16;" :: "r"(dst), "l"(src));
}
#define CP_COMMIT() asm volatile("cp.async.commit_group;")
#define CP_WAIT0()  asm volatile("cp.async.wait_group 0;")

// ---------------------------------------------------------------------------
// Kernel 0: convert x, w_qkv, w_proj to fp16
// ---------------------------------------------------------------------------
__global__ __launch_bounds__(256) void prep_kernel(
    const float* __restrict__ x, const float* __restrict__ wq,
    const float* __restrict__ wp)
{
    int i = blockIdx.x * 256 + threadIdx.x;   // float4 index
    const float4* src; uint2* dst; int off;
    if (i < XTOT / 4)                { src = (const float4*)x;  dst = (uint2*)g_Xh;  off = i; }
    else if (i < (XTOT + WQTOT) / 4) { src = (const float4*)wq; dst = (uint2*)g_Wqh; off = i - XTOT / 4; }
    else                             { src = (const float4*)wp; dst = (uint2*)g_Wph; off = i - (XTOT + WQTOT) / 4; }
    float4 v = src[off];
    dst[off] = make_uint2(packhf(v.x, v.y), packhf(v.z, v.w));
}

// ---------------------------------------------------------------------------
// Kernel 1: QKV = gather(g_Xh, idx) @ g_Wqh^T  (fp16 m16n8k16 mma)
// tile 128x128, 8 warps (4m x 2n), warp tile 32x64, k-slab 32, 2-stage.
// Epilogue: Q -> fp16 pre-scaled; K,V -> fp16 hi/lo. grid (6, 128), 256 thr.
// ---------------------------------------------------------------------------
#define HP 40                        // fp16 pitch
#define HSTGE (256 * HP)             // fp16 elems per stage
#define HSTGB (HSTGE * 2)            // bytes per stage (20480)

__global__ __launch_bounds__(256) void qkv_kernel(const int* __restrict__ idx)
{
    const int cBase = blockIdx.x * 128;
    const int rblk  = blockIdx.y;
    const int b     = rblk >> 5;
    const int jBase = (rblk & 31) * 128;

    __shared__ __half sbuf[2][256][HP];
    __shared__ int    sidx[128];

    const int tid = threadIdx.x;
    const int warp = tid >> 5, lane = tid & 31;
    const int g = lane >> 2, t = lane & 3;
    const int wm = warp >> 1, wn = warp & 1;
    const int mat = lane >> 3, r8 = lane & 7;

    if (tid < 128) sidx[tid] = idx[jBase + tid];
    __syncthreads();

    const __half* aG = g_Xh + ((size_t)b * NN + sidx[tid >> 1]) * CC + (tid & 1) * 16;
    const __half* bG = g_Wqh + (size_t)(cBase + (tid >> 1)) * CC + (tid & 1) * 16;
    const uint32_t aDst = sptr(&sbuf[0][tid >> 1][(tid & 1) * 16]);
    const uint32_t bDst = sptr(&sbuf[0][128 + (tid >> 1)][(tid & 1) * 16]);

    const uint32_t aAddr0 = sptr(&sbuf[0][wm * 32 + (mat & 1) * 8 + r8][(mat >> 1) * 8]);
    const uint32_t bAddr0 = sptr(&sbuf[0][128 + wn * 64 + (mat >> 1) * 8 + r8][(mat & 1) * 8]);

#define HFILL(st, s) do {                                 \
        cpa16(aDst + (st) * HSTGB,      aG + (s) * 32);   \
        cpa16(aDst + (st) * HSTGB + 16, aG + (s) * 32 + 8); \
        cpa16(bDst + (st) * HSTGB,      bG + (s) * 32);   \
        cpa16(bDst + (st) * HSTGB + 16, bG + (s) * 32 + 8); \
        CP_COMMIT();                                       \
    } while (0)

    float acc[2][8][4] = {};

    HFILL(0, 0);

    for (int s = 0; s < 8; s++) {
        CP_WAIT0();
        __syncthreads();
        if (s < 7) HFILL((s + 1) & 1, s + 1);

        const uint32_t aA = aAddr0 + (s & 1) * HSTGB;
        const uint32_t bA = bAddr0 + (s & 1) * HSTGB;
#pragma unroll
        for (int ks = 0; ks < 2; ks++) {
            uint32_t af[2][4];
#pragma unroll
            for (int mt = 0; mt < 2; mt++)
                ldsm4(aA + (uint32_t)(mt * 16 * HP + ks * 16) * 2,
                      af[mt][0], af[mt][1], af[mt][2], af[mt][3]);
#pragma unroll
            for (int p = 0; p < 4; p++) {
                uint32_t bf[4];
                ldsm4(bA + (uint32_t)(p * 16 * HP + ks * 16) * 2,
                      bf[0], bf[1], bf[2], bf[3]);
                mma16h(acc[0][p * 2],     af[0], bf[0], bf[1]);
                mma16h(acc[1][p * 2],     af[1], bf[0], bf[1]);
                mma16h(acc[0][p * 2 + 1], af[0], bf[2], bf[3]);
                mma16h(acc[1][p * 2 + 1], af[1], bf[2], bf[3]);
            }
        }
    }

    // Epilogue
    const int cwb = cBase + wn * 64;
    const int s2 = cwb >> 8;
#pragma unroll
    for (int mt = 0; mt < 2; mt++) {
#pragma unroll
        for (int r = 0; r < 2; r++) {
            int j = jBase + wm * 32 + mt * 16 + g + r * 8;
            int gg = j >> 10, i = j & 1023;
#pragma unroll
            for (int nt = 0; nt < 8; nt++) {
                int c0 = cwb + nt * 8;
                int h = (c0 >> 5) & 7;
                int dd = (c0 & 31) + 2 * t;
                int bgh = (b * GG + gg) * HH + h;
                float v0 = acc[mt][nt][r * 2], v1 = acc[mt][nt][r * 2 + 1];
                size_t off = (size_t)bgh * NG * DD + (size_t)i * DD + dd;
                if (s2 == 0) {
                    *(uint32_t*)&g_Qh[off] = packhf(v0 * QSCL, v1 * QSCL);
                } else {
                    uint32_t hp, lp;
                    splithf(v0, v1, hp, lp);
                    __half* dh = (s2 == 1) ? g_Khi : g_Vhi;
                    __half* dl = (s2 == 1) ? g_Klo : g_Vlo;
                    *(uint32_t*)&dh[off] = hp;
                    *(uint32_t*)&dl[off] = lp;
                }
            }
        }
    }
}

// ---------------------------------------------------------------------------
// Kernel 2: flash attention, static softmax.
// S: fp16 2-term (qh x (kh + kl)). PV: fp16 P x fp16 V hi/lo (2 MMAs).
// 256 threads, grid (8, 128). O written fp16.
// ---------------------------------------------------------------------------
#define KP 40
#define KSTG (64 * KP * 2)

__global__ __launch_bounds__(256) void attn_kernel()
{
    const int bgh = blockIdx.y;

    __shared__ __half sKh[2][64][KP];
    __shared__ __half sKl[2][64][KP];
    __shared__ __half sVh[2][64][KP];
    __shared__ __half sVl[2][64][KP];

    const int tid = threadIdx.x;
    const int warp = tid >> 5, lane = tid & 31;
    const int g = lane >> 2, t = lane & 3;
    const int mat = lane >> 3, r8 = lane & 7;
    const int rbase = warp * 16;

    const size_t srcOff = (size_t)bgh * NG * DD + (tid >> 2) * 32 + (tid & 3) * 8;
    const __half* kSrcH = g_Khi + srcOff;
    const __half* kSrcL = g_Klo + srcOff;
    const __half* vSrcH = g_Vhi + srcOff;
    const __half* vSrcL = g_Vlo + srcOff;
    const uint32_t kDstH = sptr(&sKh[0][tid >> 2][(tid & 3) * 8]);
    const uint32_t kDstL = sptr(&sKl[0][tid >> 2][(tid & 3) * 8]);
    const uint32_t vDstH = sptr(&sVh[0][tid >> 2][(tid & 3) * 8]);
    const uint32_t vDstL = sptr(&sVl[0][tid >> 2][(tid & 3) * 8]);

#define ATTN_FILL(buf, kb) do {                                   \
        cpa16(kDstH + (buf) * KSTG, kSrcH + (size_t)(kb) * 2048); \
        cpa16(kDstL + (buf) * KSTG, kSrcL + (size_t)(kb) * 2048); \
        cpa16(vDstH + (buf) * KSTG, vSrcH + (size_t)(kb) * 2048); \
        cpa16(vDstL + (buf) * KSTG, vSrcL + (size_t)(kb) * 2048); \
    } while (0)

    ATTN_FILL(0, 0);
    CP_COMMIT();

    const uint32_t kAddrH = sptr(&sKh[0][(mat >> 1) * 8 + r8][(mat & 1) * 8]);
    const uint32_t kAddrL = sptr(&sKl[0][(mat >> 1) * 8 + r8][(mat & 1) * 8]);
    const uint32_t vAddrH = sptr(&sVh[0][(mat & 1) * 8 + r8][(mat >> 1) * 8]);
    const uint32_t vAddrL = sptr(&sVl[0][(mat & 1) * 8 + r8][(mat >> 1) * 8]);

    // Q fragments: direct u32 loads (g_Qh is pre-scaled fp16)
    uint32_t qh[2][4];
    {
        const __half* Qw = g_Qh + (size_t)bgh * NG * DD
                         + (size_t)(blockIdx.x * 128 + rbase) * DD;
#pragma unroll
        for (int s = 0; s < 2; s++) {
            qh[s][0] = *(const uint32_t*)&Qw[g * 32 + s * 16 + 2 * t];
            qh[s][1] = *(const uint32_t*)&Qw[(g + 8) * 32 + s * 16 + 2 * t];
            qh[s][2] = *(const uint32_t*)&Qw[g * 32 + s * 16 + 8 + 2 * t];
            qh[s][3] = *(const uint32_t*)&Qw[(g + 8) * 32 + s * 16 + 8 + 2 * t];
        }
    }

    float l0a = 0.f, l1a = 0.f;
    float oc[4][4] = {};

    for (int kb = 0; kb < 16; kb++) {
        const int cur = kb & 1;
        CP_WAIT0();
        __syncthreads();
        if (kb < 15) {
            ATTN_FILL(cur ^ 1, kb + 1);
            CP_COMMIT();
        }

        // --- S = Q K^T (fp16 2-term) ---
        float sc[8][4];
#pragma unroll
        for (int nt = 0; nt < 8; nt++)
            sc[nt][0] = sc[nt][1] = sc[nt][2] = sc[nt][3] = 0.f;
#pragma unroll
        for (int s = 0; s < 2; s++) {
#pragma unroll
            for (int p = 0; p < 4; p++) {
                const uint32_t off = cur * KSTG + (uint32_t)(p * 16 * KP + s * 16) * 2;
                uint32_t kh[4], kl[4];
                ldsm4(kAddrH + off, kh[0], kh[1], kh[2], kh[3]);
                ldsm4(kAddrL + off, kl[0], kl[1], kl[2], kl[3]);
                mma16h(sc[p * 2],     qh[s], kh[0], kh[1]);
                mma16h(sc[p * 2],     qh[s], kl[0], kl[1]);
                mma16h(sc[p * 2 + 1], qh[s], kh[2], kh[3]);
                mma16h(sc[p * 2 + 1], qh[s], kl[2], kl[3]);
            }
        }

        // --- static softmax: p = 2^sc ---
#pragma unroll
        for (int nt = 0; nt < 8; nt++) {
            sc[nt][0] = ex2(sc[nt][0]); l0a += sc[nt][0];
            sc[nt][1] = ex2(sc[nt][1]); l0a += sc[nt][1];
            sc[nt][2] = ex2(sc[nt][2]); l1a += sc[nt][2];
            sc[nt][3] = ex2(sc[nt][3]); l1a += sc[nt][3];
        }

        // --- O += P @ V (fp16 P x fp16 V hi/lo) ---
#pragma unroll
        for (int s = 0; s < 4; s++) {
            uint32_t ap[4];
            ap[0] = packhf(sc[2 * s][0],     sc[2 * s][1]);
            ap[1] = packhf(sc[2 * s][2],     sc[2 * s][3]);
            ap[2] = packhf(sc[2 * s + 1][0], sc[2 * s + 1][1]);
            ap[3] = packhf(sc[2 * s + 1][2], sc[2 * s + 1][3]);
            const uint32_t off = cur * KSTG + (uint32_t)(s * 16 * KP) * 2;
            uint32_t vh[4], vl[4];
            ldsm4t(vAddrH + off, vh[0], vh[1], vh[2], vh[3]);
            ldsm4t(vAddrL + off, vl[0], vl[1], vl[2], vl[3]);
            mma16h(oc[0], ap, vh[0], vh[1]);
            mma16h(oc[0], ap, vl[0], vl[1]);
            mma16h(oc[1], ap, vh[2], vh[3]);
            mma16h(oc[1], ap, vl[2], vl[3]);
            const uint32_t off2 = off + 16 * 2;
            ldsm4t(vAddrH + off2, vh[0], vh[1], vh[2], vh[3]);
            ldsm4t(vAddrL + off2, vl[0], vl[1], vl[2], vl[3]);
            mma16h(oc[2], ap, vh[0], vh[1]);
            mma16h(oc[2], ap, vl[0], vl[1]);
            mma16h(oc[3], ap, vh[2], vh[3]);
            mma16h(oc[3], ap, vl[2], vl[3]);
        }
    }

    l0a += __shfl_xor_sync(0xffffffffu, l0a, 1);
    l0a += __shfl_xor_sync(0xffffffffu, l0a, 2);
    l1a += __shfl_xor_sync(0xffffffffu, l1a, 1);
    l1a += __shfl_xor_sync(0xffffffffu, l1a, 2);

    const int b = bgh >> 5, gg = (bgh >> 3) & 3, h = bgh & 7;
    float inv0 = 1.f / l0a, inv1 = 1.f / l1a;
    int i0 = blockIdx.x * 128 + rbase + g;
    size_t row0 = ((size_t)b * NN + (size_t)gg * NG + i0) * CC + h * DD;
    size_t row1 = row0 + (size_t)8 * CC;
#pragma unroll
    for (int nt = 0; nt < 4; nt++) {
        *(uint32_t*)&g_Oh[row0 + nt * 8 + 2 * t] =
            packhf(oc[nt][0] * inv0, oc[nt][1] * inv0);
        *(uint32_t*)&g_Oh[row1 + nt * 8 + 2 * t] =
            packhf(oc[nt][2] * inv1, oc[nt][3] * inv1);
    }
}

// ---------------------------------------------------------------------------
// Kernel 3: out[b, idx[j], :] = g_Oh[b, j, :] @ g_Wph^T + bias  (fp16 mma)
// 128x128 tile, grid (2, 128), 256 thr.
// ---------------------------------------------------------------------------
__global__ __launch_bounds__(256) void proj_kernel(
    const int* __restrict__ idx, const float* __restrict__ bias,
    float* __restrict__ out)
{
    const int cBase = blockIdx.x * 128;
    const int rblk  = blockIdx.y;
    const int b     = rblk >> 5;
    const int jBase = (rblk & 31) * 128;

    __shared__ __half sbuf[2][256][HP];
    __shared__ int    sidx[128];

    const int tid = threadIdx.x;
    const int warp = tid >> 5, lane = tid & 31;
    const int g = lane >> 2, t = lane & 3;
    const int wm = warp >> 1, wn = warp & 1;
    const int mat = lane >> 3, r8 = lane & 7;

    if (tid < 128) sidx[tid] = idx[jBase + tid];
    __syncthreads();

    const __half* aG = g_Oh + ((size_t)b * NN + jBase + (tid >> 1)) * CC + (tid & 1) * 16;
    const __half* bG = g_Wph + (size_t)(cBase + (tid >> 1)) * CC + (tid & 1) * 16;
    const uint32_t aDst = sptr(&sbuf[0][tid >> 1][(tid & 1) * 16]);
    const uint32_t bDst = sptr(&sbuf[0][128 + (tid >> 1)][(tid & 1) * 16]);

    const uint32_t aAddr0 = sptr(&sbuf[0][wm * 32 + (mat & 1) * 8 + r8][(mat >> 1) * 8]);
    const uint32_t bAddr0 = sptr(&sbuf[0][128 + wn * 64 + (mat >> 1) * 8 + r8][(mat & 1) * 8]);

    float acc[2][8][4] = {};

    HFILL(0, 0);

    for (int s = 0; s < 8; s++) {
        CP_WAIT0();
        __syncthreads();
        if (s < 7) HFILL((s + 1) & 1, s + 1);

        const uint32_t aA = aAddr0 + (s & 1) * HSTGB;
        const uint32_t bA = bAddr0 + (s & 1) * HSTGB;
#pragma unroll
        for (int ks = 0; ks < 2; ks++) {
            uint32_t af[2][4];
#pragma unroll
            for (int mt = 0; mt < 2; mt++)
                ldsm4(aA + (uint32_t)(mt * 16 * HP + ks * 16) * 2,
                      af[mt][0], af[mt][1], af[mt][2], af[mt][3]);
#pragma unroll
            for (int p = 0; p < 4; p++) {
                uint32_t bf[4];
                ldsm4(bA + (uint32_t)(p * 16 * HP + ks * 16) * 2,
                      bf[0], bf[1], bf[2], bf[3]);
                mma16h(acc[0][p * 2],     af[0], bf[0], bf[1]);
                mma16h(acc[1][p * 2],     af[1], bf[0], bf[1]);
                mma16h(acc[0][p * 2 + 1], af[0], bf[2], bf[3]);
                mma16h(acc[1][p * 2 + 1], af[1], bf[2], bf[3]);
            }
        }
    }

    // Epilogue: bias + inverse-permutation row scatter
    const int cwb = cBase + wn * 64;
    float2 bb[8];
#pragma unroll
    for (int nt = 0; nt < 8; nt++)
        bb[nt] = *(const float2*)&bias[cwb + nt * 8 + 2 * t];

#pragma unroll
    for (int mt = 0; mt < 2; mt++) {
#pragma unroll
        for (int r = 0; r < 2; r++) {
            int jl = wm * 32 + mt * 16 + g + r * 8;
            int orow = sidx[jl];
            size_t base = ((size_t)b * NN + orow) * CC + cwb;
#pragma unroll
            for (int nt = 0; nt < 8; nt++) {
                *(float2*)&out[base + nt * 8 + 2 * t] =
                    make_float2(acc[mt][nt][r * 2] + bb[nt].x,
                                acc[mt][nt][r * 2 + 1] + bb[nt].y);
            }
        }
    }
}

// ---------------------------------------------------------------------------
extern "C" void kernel_launch(void* const* d_in, const int* in_sizes, int n_in,
                              void* d_out, int out_size)
{
    (void)in_sizes; (void)n_in; (void)out_size;
    const float* x      = (const float*)d_in[0];
    const int*   idx    = (const int*)d_in[1];
    const float* w_qkv  = (const float*)d_in[2];
    const float* w_proj = (const float*)d_in[3];
    const float* b_proj = (const float*)d_in[4];
    float* out = (float*)d_out;

    prep_kernel<<<(XTOT + WQTOT + WPTOT) / 4 / 256, 256>>>(x, w_qkv, w_proj);
    qkv_kernel<<<dim3(6, 128), 256>>>(idx);
    attn_kernel<<<dim3(8, 128), 256>>>();
    proj_kernel<<<dim3(2, 128), 256>>>(idx, b_proj, out);
}

// round 17
// speedup vs baseline: 2.4455x; 1.5487x over previous
#include <cuda_runtime.h>
#include <cuda_fp16.h>
#include <math.h>
#include <stdint.h>

// Problem constants
#define BB 4
#define NN 4096
#define CC 256
#define HH 8
#define GG 4
#define DD 32
#define NG 1024
#define QSCL (0.17677669529663687f * 1.4426950408889634f)  // 1/sqrt(32)*log2(e)

#define XTOT  (BB * NN * CC)
#define WQTOT (3 * CC * CC)
#define WPTOT (CC * CC)

// Scratch (device globals; allocation-free)
__device__ __half g_Xh[XTOT];
__device__ __half g_Wqh[WQTOT];
__device__ __half g_Wph[WPTOT];
__device__ __half g_Qh[BB * GG * HH * NG * DD];           // pre-scaled by QSCL
__device__ __half g_K[BB * GG * HH * NG * DD];            // [bgh][i][d]
__device__ __half g_V[BB * GG * HH * NG * DD];
__device__ __half g_Oh[BB * NN * CC];                     // attention out fp16

// ---------------------------------------------------------------------------
// PTX helpers
// ---------------------------------------------------------------------------
__device__ __forceinline__ void mma16h(float c[4], const uint32_t a[4],
                                       uint32_t b0, uint32_t b1) {
    asm volatile(
        "mma.sync.aligned.m16n8k16.row.col.f32.f16.f16.f32 "
        "{%0,%1,%2,%3}, {%4,%5,%6,%7}, {%8,%9}, {%0,%1,%2,%3};"
        : "+f"(c[0]), "+f"(c[1]), "+f"(c[2]), "+f"(c[3])
        : "r"(a[0]), "r"(a[1]), "r"(a[2]), "r"(a[3]), "r"(b0), "r"(b1));
}
__device__ __forceinline__ float ex2(float x) {
    float r; asm("ex2.approx.ftz.f32 %0, %1;" : "=f"(r) : "f"(x)); return r;
}
__device__ __forceinline__ uint32_t packhf(float x, float y) {
    __half2 h = __floats2half2_rn(x, y);
    return *reinterpret_cast<uint32_t*>(&h);
}
__device__ __forceinline__ uint32_t sptr(const void* p) {
    return (uint32_t)__cvta_generic_to_shared(p);
}
__device__ __forceinline__ void ldsm4(uint32_t addr, uint32_t& r0, uint32_t& r1,
                                      uint32_t& r2, uint32_t& r3) {
    asm volatile("ldmatrix.sync.aligned.m8n8.x4.shared.b16 {%0,%1,%2,%3}, [%4];"
                 : "=r"(r0), "=r"(r1), "=r"(r2), "=r"(r3) : "r"(addr));
}
__device__ __forceinline__ void ldsm4t(uint32_t addr, uint32_t& r0, uint32_t& r1,
                                       uint32_t& r2, uint32_t& r3) {
    asm volatile("ldmatrix.sync.aligned.m8n8.x4.trans.shared.b16 {%0,%1,%2,%3}, [%4];"
                 : "=r"(r0), "=r"(r1), "=r"(r2), "=r"(r3) : "r"(addr));
}
__device__ __forceinline__ void cpa16(uint32_t dst, const void* src) {
    asm volatile("cp.async.cg.shared.global [%0], [%1], 16;" :: "r"(dst), "l"(src));
}
#define CP_COMMIT() asm volatile("cp.async.commit_group;")
#define CP_WAIT0()  asm volatile("cp.async.wait_group 0;")

// ---------------------------------------------------------------------------
// Kernel 0: convert x, w_qkv, w_proj to fp16
// ---------------------------------------------------------------------------
__global__ __launch_bounds__(256) void prep_kernel(
    const float* __restrict__ x, const float* __restrict__ wq,
    const float* __restrict__ wp)
{
    int i = blockIdx.x * 256 + threadIdx.x;   // float4 index
    const float4* src; uint2* dst; int off;
    if (i < XTOT / 4)                { src = (const float4*)x;  dst = (uint2*)g_Xh;  off = i; }
    else if (i < (XTOT + WQTOT) / 4) { src = (const float4*)wq; dst = (uint2*)g_Wqh; off = i - XTOT / 4; }
    else                             { src = (const float4*)wp; dst = (uint2*)g_Wph; off = i - (XTOT + WQTOT) / 4; }
    float4 v = src[off];
    dst[off] = make_uint2(packhf(v.x, v.y), packhf(v.z, v.w));
}

// ---------------------------------------------------------------------------
// Kernel 1: QKV = gather(g_Xh, idx) @ g_Wqh^T  (fp16 m16n8k16 mma)
// tile 128x128, 8 warps (4m x 2n), warp tile 32x64, k-slab 32, 2-stage.
// Epilogue: Q pre-scaled fp16; K, V plain fp16. grid (6, 128), 256 thr.
// ---------------------------------------------------------------------------
#define HP 40                        // fp16 pitch
#define HSTGE (256 * HP)             // fp16 elems per stage
#define HSTGB (HSTGE * 2)            // bytes per stage (20480)

__global__ __launch_bounds__(256) void qkv_kernel(const int* __restrict__ idx)
{
    const int cBase = blockIdx.x * 128;
    const int rblk  = blockIdx.y;
    const int b     = rblk >> 5;
    const int jBase = (rblk & 31) * 128;

    __shared__ __half sbuf[2][256][HP];
    __shared__ int    sidx[128];

    const int tid = threadIdx.x;
    const int warp = tid >> 5, lane = tid & 31;
    const int g = lane >> 2, t = lane & 3;
    const int wm = warp >> 1, wn = warp & 1;
    const int mat = lane >> 3, r8 = lane & 7;

    if (tid < 128) sidx[tid] = idx[jBase + tid];
    __syncthreads();

    const __half* aG = g_Xh + ((size_t)b * NN + sidx[tid >> 1]) * CC + (tid & 1) * 16;
    const __half* bG = g_Wqh + (size_t)(cBase + (tid >> 1)) * CC + (tid & 1) * 16;
    const uint32_t aDst = sptr(&sbuf[0][tid >> 1][(tid & 1) * 16]);
    const uint32_t bDst = sptr(&sbuf[0][128 + (tid >> 1)][(tid & 1) * 16]);

    const uint32_t aAddr0 = sptr(&sbuf[0][wm * 32 + (mat & 1) * 8 + r8][(mat >> 1) * 8]);
    const uint32_t bAddr0 = sptr(&sbuf[0][128 + wn * 64 + (mat >> 1) * 8 + r8][(mat & 1) * 8]);

#define HFILL(st, s) do {                                   \
        cpa16(aDst + (st) * HSTGB,      aG + (s) * 32);     \
        cpa16(aDst + (st) * HSTGB + 16, aG + (s) * 32 + 8); \
        cpa16(bDst + (st) * HSTGB,      bG + (s) * 32);     \
        cpa16(bDst + (st) * HSTGB + 16, bG + (s) * 32 + 8); \
        CP_COMMIT();                                         \
    } while (0)

    float acc[2][8][4] = {};

    HFILL(0, 0);

    for (int s = 0; s < 8; s++) {
        CP_WAIT0();
        __syncthreads();
        if (s < 7) HFILL((s + 1) & 1, s + 1);

        const uint32_t aA = aAddr0 + (s & 1) * HSTGB;
        const uint32_t bA = bAddr0 + (s & 1) * HSTGB;
#pragma unroll
        for (int ks = 0; ks < 2; ks++) {
            uint32_t af[2][4];
#pragma unroll
            for (int mt = 0; mt < 2; mt++)
                ldsm4(aA + (uint32_t)(mt * 16 * HP + ks * 16) * 2,
                      af[mt][0], af[mt][1], af[mt][2], af[mt][3]);
#pragma unroll
            for (int p = 0; p < 4; p++) {
                uint32_t bf[4];
                ldsm4(bA + (uint32_t)(p * 16 * HP + ks * 16) * 2,
                      bf[0], bf[1], bf[2], bf[3]);
                mma16h(acc[0][p * 2],     af[0], bf[0], bf[1]);
                mma16h(acc[1][p * 2],     af[1], bf[0], bf[1]);
                mma16h(acc[0][p * 2 + 1], af[0], bf[2], bf[3]);
                mma16h(acc[1][p * 2 + 1], af[1], bf[2], bf[3]);
            }
        }
    }

    // Epilogue
    const int cwb = cBase + wn * 64;
    const int s2 = cwb >> 8;
#pragma unroll
    for (int mt = 0; mt < 2; mt++) {
#pragma unroll
        for (int r = 0; r < 2; r++) {
            int j = jBase + wm * 32 + mt * 16 + g + r * 8;
            int gg = j >> 10, i = j & 1023;
#pragma unroll
            for (int nt = 0; nt < 8; nt++) {
                int c0 = cwb + nt * 8;
                int h = (c0 >> 5) & 7;
                int dd = (c0 & 31) + 2 * t;
                int bgh = (b * GG + gg) * HH + h;
                float v0 = acc[mt][nt][r * 2], v1 = acc[mt][nt][r * 2 + 1];
                size_t off = (size_t)bgh * NG * DD + (size_t)i * DD + dd;
                if (s2 == 0) {
                    *(uint32_t*)&g_Qh[off] = packhf(v0 * QSCL, v1 * QSCL);
                } else {
                    __half* dh = (s2 == 1) ? g_K : g_V;
                    *(uint32_t*)&dh[off] = packhf(v0, v1);
                }
            }
        }
    }
}

// ---------------------------------------------------------------------------
// Kernel 2: flash attention, static softmax, single-term fp16 S and PV.
// 256 threads, grid (8, 128). O written fp16.
// ---------------------------------------------------------------------------
#define KP 40
#define KSTG (64 * KP * 2)

__global__ __launch_bounds__(256) void attn_kernel()
{
    const int bgh = blockIdx.y;

    __shared__ __half sK[2][64][KP];
    __shared__ __half sV[2][64][KP];

    const int tid = threadIdx.x;
    const int warp = tid >> 5, lane = tid & 31;
    const int g = lane >> 2, t = lane & 3;
    const int mat = lane >> 3, r8 = lane & 7;
    const int rbase = warp * 16;

    const size_t srcOff = (size_t)bgh * NG * DD + (tid >> 2) * 32 + (tid & 3) * 8;
    const __half* kSrc = g_K + srcOff;
    const __half* vSrc = g_V + srcOff;
    const uint32_t kDst = sptr(&sK[0][tid >> 2][(tid & 3) * 8]);
    const uint32_t vDst = sptr(&sV[0][tid >> 2][(tid & 3) * 8]);

#define ATTN_FILL(buf, kb) do {                                \
        cpa16(kDst + (buf) * KSTG, kSrc + (size_t)(kb) * 2048); \
        cpa16(vDst + (buf) * KSTG, vSrc + (size_t)(kb) * 2048); \
    } while (0)

    ATTN_FILL(0, 0);
    CP_COMMIT();

    const uint32_t kAddr = sptr(&sK[0][(mat >> 1) * 8 + r8][(mat & 1) * 8]);
    const uint32_t vAddr = sptr(&sV[0][(mat & 1) * 8 + r8][(mat >> 1) * 8]);

    // Q fragments: direct u32 loads (g_Qh pre-scaled fp16)
    uint32_t qh[2][4];
    {
        const __half* Qw = g_Qh + (size_t)bgh * NG * DD
                         + (size_t)(blockIdx.x * 128 + rbase) * DD;
#pragma unroll
        for (int s = 0; s < 2; s++) {
            qh[s][0] = *(const uint32_t*)&Qw[g * 32 + s * 16 + 2 * t];
            qh[s][1] = *(const uint32_t*)&Qw[(g + 8) * 32 + s * 16 + 2 * t];
            qh[s][2] = *(const uint32_t*)&Qw[g * 32 + s * 16 + 8 + 2 * t];
            qh[s][3] = *(const uint32_t*)&Qw[(g + 8) * 32 + s * 16 + 8 + 2 * t];
        }
    }

    float l0a = 0.f, l1a = 0.f;
    float oc[4][4] = {};

    for (int kb = 0; kb < 16; kb++) {
        const int cur = kb & 1;
        CP_WAIT0();
        __syncthreads();
        if (kb < 15) {
            ATTN_FILL(cur ^ 1, kb + 1);
            CP_COMMIT();
        }

        // --- S = Q K^T (single-term fp16) ---
        float sc[8][4];
#pragma unroll
        for (int nt = 0; nt < 8; nt++)
            sc[nt][0] = sc[nt][1] = sc[nt][2] = sc[nt][3] = 0.f;
#pragma unroll
        for (int s = 0; s < 2; s++) {
#pragma unroll
            for (int p = 0; p < 4; p++) {
                const uint32_t off = cur * KSTG + (uint32_t)(p * 16 * KP + s * 16) * 2;
                uint32_t kf[4];
                ldsm4(kAddr + off, kf[0], kf[1], kf[2], kf[3]);
                mma16h(sc[p * 2],     qh[s], kf[0], kf[1]);
                mma16h(sc[p * 2 + 1], qh[s], kf[2], kf[3]);
            }
        }

        // --- static softmax: p = 2^sc ---
#pragma unroll
        for (int nt = 0; nt < 8; nt++) {
            sc[nt][0] = ex2(sc[nt][0]); l0a += sc[nt][0];
            sc[nt][1] = ex2(sc[nt][1]); l0a += sc[nt][1];
            sc[nt][2] = ex2(sc[nt][2]); l1a += sc[nt][2];
            sc[nt][3] = ex2(sc[nt][3]); l1a += sc[nt][3];
        }

        // --- O += P @ V (fp16 P x fp16 V, single-term) ---
#pragma unroll
        for (int s = 0; s < 4; s++) {
            uint32_t ap[4];
            ap[0] = packhf(sc[2 * s][0],     sc[2 * s][1]);
            ap[1] = packhf(sc[2 * s][2],     sc[2 * s][3]);
            ap[2] = packhf(sc[2 * s + 1][0], sc[2 * s + 1][1]);
            ap[3] = packhf(sc[2 * s + 1][2], sc[2 * s + 1][3]);
            const uint32_t off = cur * KSTG + (uint32_t)(s * 16 * KP) * 2;
            uint32_t vf[4];
            ldsm4t(vAddr + off, vf[0], vf[1], vf[2], vf[3]);
            mma16h(oc[0], ap, vf[0], vf[1]);
            mma16h(oc[1], ap, vf[2], vf[3]);
            ldsm4t(vAddr + off + 16 * 2, vf[0], vf[1], vf[2], vf[3]);
            mma16h(oc[2], ap, vf[0], vf[1]);
            mma16h(oc[3], ap, vf[2], vf[3]);
        }
    }

    l0a += __shfl_xor_sync(0xffffffffu, l0a, 1);
    l0a += __shfl_xor_sync(0xffffffffu, l0a, 2);
    l1a += __shfl_xor_sync(0xffffffffu, l1a, 1);
    l1a += __shfl_xor_sync(0xffffffffu, l1a, 2);

    const int b = bgh >> 5, gg = (bgh >> 3) & 3, h = bgh & 7;
    float inv0 = 1.f / l0a, inv1 = 1.f / l1a;
    int i0 = blockIdx.x * 128 + rbase + g;
    size_t row0 = ((size_t)b * NN + (size_t)gg * NG + i0) * CC + h * DD;
    size_t row1 = row0 + (size_t)8 * CC;
#pragma unroll
    for (int nt = 0; nt < 4; nt++) {
        *(uint32_t*)&g_Oh[row0 + nt * 8 + 2 * t] =
            packhf(oc[nt][0] * inv0, oc[nt][1] * inv0);
        *(uint32_t*)&g_Oh[row1 + nt * 8 + 2 * t] =
            packhf(oc[nt][2] * inv1, oc[nt][3] * inv1);
    }
}

// ---------------------------------------------------------------------------
// Kernel 3: out[b, idx[j], :] = g_Oh[b, j, :] @ g_Wph^T + bias  (fp16 mma)
// 128x128 tile, grid (2, 128), 256 thr.
// ---------------------------------------------------------------------------
__global__ __launch_bounds__(256) void proj_kernel(
    const int* __restrict__ idx, const float* __restrict__ bias,
    float* __restrict__ out)
{
    const int cBase = blockIdx.x * 128;
    const int rblk  = blockIdx.y;
    const int b     = rblk >> 5;
    const int jBase = (rblk & 31) * 128;

    __shared__ __half sbuf[2][256][HP];
    __shared__ int    sidx[128];

    const int tid = threadIdx.x;
    const int warp = tid >> 5, lane = tid & 31;
    const int g = lane >> 2, t = lane & 3;
    const int wm = warp >> 1, wn = warp & 1;
    const int mat = lane >> 3, r8 = lane & 7;

    if (tid < 128) sidx[tid] = idx[jBase + tid];
    __syncthreads();

    const __half* aG = g_Oh + ((size_t)b * NN + jBase + (tid >> 1)) * CC + (tid & 1) * 16;
    const __half* bG = g_Wph + (size_t)(cBase + (tid >> 1)) * CC + (tid & 1) * 16;
    const uint32_t aDst = sptr(&sbuf[0][tid >> 1][(tid & 1) * 16]);
    const uint32_t bDst = sptr(&sbuf[0][128 + (tid >> 1)][(tid & 1) * 16]);

    const uint32_t aAddr0 = sptr(&sbuf[0][wm * 32 + (mat & 1) * 8 + r8][(mat >> 1) * 8]);
    const uint32_t bAddr0 = sptr(&sbuf[0][128 + wn * 64 + (mat >> 1) * 8 + r8][(mat & 1) * 8]);

    float acc[2][8][4] = {};

    HFILL(0, 0);

    for (int s = 0; s < 8; s++) {
        CP_WAIT0();
        __syncthreads();
        if (s < 7) HFILL((s + 1) & 1, s + 1);

        const uint32_t aA = aAddr0 + (s & 1) * HSTGB;
        const uint32_t bA = bAddr0 + (s & 1) * HSTGB;
#pragma unroll
        for (int ks = 0; ks < 2; ks++) {
            uint32_t af[2][4];
#pragma unroll
            for (int mt = 0; mt < 2; mt++)
                ldsm4(aA + (uint32_t)(mt * 16 * HP + ks * 16) * 2,
                      af[mt][0], af[mt][1], af[mt][2], af[mt][3]);
#pragma unroll
            for (int p = 0; p < 4; p++) {
                uint32_t bf[4];
                ldsm4(bA + (uint32_t)(p * 16 * HP + ks * 16) * 2,
                      bf[0], bf[1], bf[2], bf[3]);
                mma16h(acc[0][p * 2],     af[0], bf[0], bf[1]);
                mma16h(acc[1][p * 2],     af[1], bf[0], bf[1]);
                mma16h(acc[0][p * 2 + 1], af[0], bf[2], bf[3]);
                mma16h(acc[1][p * 2 + 1], af[1], bf[2], bf[3]);
            }
        }
    }

    // Epilogue: bias + inverse-permutation row scatter
    const int cwb = cBase + wn * 64;
    float2 bb[8];
#pragma unroll
    for (int nt = 0; nt < 8; nt++)
        bb[nt] = *(const float2*)&bias[cwb + nt * 8 + 2 * t];

#pragma unroll
    for (int mt = 0; mt < 2; mt++) {
#pragma unroll
        for (int r = 0; r < 2; r++) {
            int jl = wm * 32 + mt * 16 + g + r * 8;
            int orow = sidx[jl];
            size_t base = ((size_t)b * NN + orow) * CC + cwb;
#pragma unroll
            for (int nt = 0; nt < 8; nt++) {
                *(float2*)&out[base + nt * 8 + 2 * t] =
                    make_float2(acc[mt][nt][r * 2] + bb[nt].x,
                                acc[mt][nt][r * 2 + 1] + bb[nt].y);
            }
        }
    }
}

// ---------------------------------------------------------------------------
extern "C" void kernel_launch(void* const* d_in, const int* in_sizes, int n_in,
                              void* d_out, int out_size)
{
    (void)in_sizes; (void)n_in; (void)out_size;
    const float* x      = (const float*)d_in[0];
    const int*   idx    = (const int*)d_in[1];
    const float* w_qkv  = (const float*)d_in[2];
    const float* w_proj = (const float*)d_in[3];
    const float* b_proj = (const float*)d_in[4];
    float* out = (float*)d_out;

    prep_kernel<<<(XTOT + WQTOT + WPTOT) / 4 / 256, 256>>>(x, w_qkv, w_proj);
    qkv_kernel<<<dim3(6, 128), 256>>>(idx);
    attn_kernel<<<dim3(8, 128), 256>>>();
    proj_kernel<<<dim3(2, 128), 256>>>(idx, b_proj, out);
}